// round 4
// baseline (speedup 1.0000x reference)
#include <cuda_runtime.h>
#include <math.h>
#include <stdint.h>

#define TT   1024
#define SSZ  1024
#define BB   4
#define DD   1024
#define HH   16
#define HDD  64
#define FFND 4096
#define MM   (TT*BB)

// ---------------- scratch (device globals; no allocs allowed) ----------------
__device__ float g_q[MM*DD];
__device__ float g_k[MM*DD];
__device__ float g_v[MM*DD];
__device__ float g_ctx[MM*DD];
__device__ float g_tmp[MM*DD];
__device__ float g_x1[MM*DD];
__device__ float g_x2[MM*DD];
__device__ float g_ffn[(size_t)MM*FFND];
__device__ float g_scores[(size_t)BB*HH*TT*SSZ];
__device__ float g_rs_self[MM];
__device__ float g_rs_enc[MM];

// ---------------- helpers ----------------
__device__ __forceinline__ float block_sum(float v) {
    __shared__ float sh[8];
    __shared__ float res;
    int lane = threadIdx.x & 31, w = threadIdx.x >> 5;
    #pragma unroll
    for (int o = 16; o > 0; o >>= 1) v += __shfl_xor_sync(0xffffffffu, v, o);
    __syncthreads();
    if (lane == 0) sh[w] = v;
    __syncthreads();
    if (threadIdx.x == 0) {
        float t = 0.f;
        #pragma unroll
        for (int i = 0; i < 8; i++) t += sh[i];
        res = t;
    }
    __syncthreads();
    return res;
}

__device__ __forceinline__ float block_max(float v) {
    __shared__ float sh[8];
    __shared__ float res;
    int lane = threadIdx.x & 31, w = threadIdx.x >> 5;
    #pragma unroll
    for (int o = 16; o > 0; o >>= 1) v = fmaxf(v, __shfl_xor_sync(0xffffffffu, v, o));
    __syncthreads();
    if (lane == 0) sh[w] = v;
    __syncthreads();
    if (threadIdx.x == 0) {
        float t = sh[0];
        #pragma unroll
        for (int i = 1; i < 8; i++) t = fmaxf(t, sh[i]);
        res = t;
    }
    __syncthreads();
    return res;
}

__device__ __forceinline__ uint32_t f2tf32(float x) {
    uint32_t u;
    asm("cvt.rna.tf32.f32 %0, %1;" : "=r"(u) : "f"(x));
    return u;
}

__device__ __forceinline__ void mma_tf32(float* d, const uint32_t* a, uint32_t b0, uint32_t b1) {
    asm volatile(
        "mma.sync.aligned.m16n8k8.row.col.f32.tf32.tf32.f32 "
        "{%0,%1,%2,%3}, {%4,%5,%6,%7}, {%8,%9}, {%0,%1,%2,%3};"
        : "+f"(d[0]), "+f"(d[1]), "+f"(d[2]), "+f"(d[3])
        : "r"(a[0]), "r"(a[1]), "r"(a[2]), "r"(a[3]), "r"(b0), "r"(b1));
}

// packed fragment layout: word(r, k) = (k>>3)*rowblk + r*8 + (k&3)*2 + ((k>>2)&1)
// => LDS.64 at (r, ks*8+tig) yields {k=kb+tig, k=kb+tig+4}

__global__ void expand_mask_kernel(const int* __restrict__ mask,
                                   float* __restrict__ rowscale, int L) {
    int r = blockIdx.x * blockDim.x + threadIdx.x;
    if (r < L * BB) {
        int pos = r / BB, b = r % BB;
        rowscale[r] = mask[b * L + pos] ? 0.f : 1.f;
    }
}

// =====================================================================
// TF32 GEMM (multi-set): C[M,N] = A[M,K] @ W[N,K]^T + bias, blockIdx.z
// selects weight set. 128x128x32 tile, 256 thr, double-buffered smem,
// LDS.64 fragment loads. Dynamic smem = 2 * (4096+4096) * 4 = 64KB.
// =====================================================================
struct GemmSet { const float* W; const float* bias; const float* rs; float* C; };

__global__ __launch_bounds__(256) void gemm_tf32_kernel(
    const float* __restrict__ A, GemmSet s0, GemmSet s1, GemmSet s2,
    int M, int N, int K, int relu)
{
    extern __shared__ uint32_t sm[];
    const GemmSet S = (blockIdx.z == 0) ? s0 : (blockIdx.z == 1 ? s1 : s2);
    const float* __restrict__ W = S.W;
    const float* __restrict__ bias = S.bias;
    const float* __restrict__ rowscale = S.rs;
    float* __restrict__ C = S.C;

    const int tid = threadIdx.x;
    const int lane = tid & 31, warp = tid >> 5;
    const int wm = warp & 3, wn = warp >> 2;
    const int g = lane >> 2, tig = lane & 3;
    const int bx = blockIdx.x, by = blockIdx.y;

    float d[2][8][4];
    #pragma unroll
    for (int mt = 0; mt < 2; mt++)
        #pragma unroll
        for (int nt = 0; nt < 8; nt++)
            #pragma unroll
            for (int i = 0; i < 4; i++) d[mt][nt][i] = 0.f;

    float4 aReg[4], wReg[4];
    float ascale[4];
    int arow[4], wrow[4];
    int sbase[4];
    #pragma unroll
    for (int i = 0; i < 4; i++) {
        int f = tid + (i << 8);
        int r = f >> 3;
        int c4 = (f & 7) << 2;
        arow[i] = by * 128 + r;
        wrow[i] = bx * 128 + r;
        sbase[i] = ((c4 >> 3) << 10) + (r << 3) + ((c4 >> 2) & 1);
        ascale[i] = rowscale ? rowscale[arow[i]] : 1.f;
    }
    const int acol = ((tid & 7) << 2);  // per-i identical pattern offset handled in sbase

    auto load_regs = [&](int k0) {
        #pragma unroll
        for (int i = 0; i < 4; i++) {
            int c4 = (((tid + (i << 8)) & 7) << 2);
            aReg[i] = *(const float4*)(A + (size_t)arow[i] * K + k0 + c4);
            wReg[i] = *(const float4*)(W + (size_t)wrow[i] * K + k0 + c4);
        }
    };
    auto store_smem = [&](uint32_t* Ab, uint32_t* Wb) {
        #pragma unroll
        for (int i = 0; i < 4; i++) {
            int bse = sbase[i];
            float s = ascale[i];
            Ab[bse + 0] = f2tf32(aReg[i].x * s);
            Ab[bse + 2] = f2tf32(aReg[i].y * s);
            Ab[bse + 4] = f2tf32(aReg[i].z * s);
            Ab[bse + 6] = f2tf32(aReg[i].w * s);
            Wb[bse + 0] = f2tf32(wReg[i].x);
            Wb[bse + 2] = f2tf32(wReg[i].y);
            Wb[bse + 4] = f2tf32(wReg[i].z);
            Wb[bse + 6] = f2tf32(wReg[i].w);
        }
    };

    const int ar0 = (wm * 32 + g) * 8 + tig * 2;
    const int bc0 = (wn * 64 + g) * 8 + tig * 2;

    auto mma_stage = [&](const uint32_t* Ab, const uint32_t* Wb) {
        #pragma unroll
        for (int ks = 0; ks < 4; ks++) {
            int ab = (ks << 10);
            uint2 a00 = *(const uint2*)&Ab[ab + ar0];
            uint2 a01 = *(const uint2*)&Ab[ab + ar0 + 64];
            uint2 a10 = *(const uint2*)&Ab[ab + ar0 + 128];
            uint2 a11 = *(const uint2*)&Ab[ab + ar0 + 192];
            uint32_t af0[4] = {a00.x, a01.x, a00.y, a01.y};
            uint32_t af1[4] = {a10.x, a11.x, a10.y, a11.y};
            #pragma unroll
            for (int nt = 0; nt < 8; nt++) {
                uint2 bb = *(const uint2*)&Wb[ab + bc0 + nt * 64];
                mma_tf32(d[0][nt], af0, bb.x, bb.y);
                mma_tf32(d[1][nt], af1, bb.x, bb.y);
            }
        }
    };

    load_regs(0);
    store_smem(sm, sm + 4096);
    __syncthreads();
    int stage = 0;
    for (int k0 = 0; k0 < K; k0 += 32) {
        bool nxt = (k0 + 32) < K;
        if (nxt) load_regs(k0 + 32);
        uint32_t* base = sm + stage * 8192;
        mma_stage(base, base + 4096);
        if (nxt) {
            int ns = stage ^ 1;
            uint32_t* nb = sm + ns * 8192;
            store_smem(nb, nb + 4096);
            __syncthreads();
            stage = ns;
        }
    }
    (void)acol;

    #pragma unroll
    for (int mt = 0; mt < 2; mt++) {
        int row0 = by * 128 + wm * 32 + mt * 16 + g;
        #pragma unroll
        for (int nt = 0; nt < 8; nt++) {
            int col = bx * 128 + wn * 64 + nt * 8 + tig * 2;
            float b0 = bias[col], b1 = bias[col + 1];
            float v00 = d[mt][nt][0] + b0, v01 = d[mt][nt][1] + b1;
            float v10 = d[mt][nt][2] + b0, v11 = d[mt][nt][3] + b1;
            if (relu) {
                v00 = fmaxf(v00, 0.f); v01 = fmaxf(v01, 0.f);
                v10 = fmaxf(v10, 0.f); v11 = fmaxf(v11, 0.f);
            }
            *(float2*)(C + (size_t)row0 * N + col)       = make_float2(v00, v01);
            *(float2*)(C + (size_t)(row0 + 8) * N + col) = make_float2(v10, v11);
        }
    }
}

// =====================================================================
// TF32 scores: Sc[bh,t,s] = scale*(Q@K^T) + mask. Whole K=64 resident
// in smem ([8][128][8] per matrix = 32KB each), single sync.
// =====================================================================
__global__ __launch_bounds__(256) void scores_tf32_kernel(
    const float* __restrict__ Q, const float* __restrict__ Kk,
    const float* __restrict__ mask, float* __restrict__ Sc, float scale)
{
    extern __shared__ uint32_t sm[];
    uint32_t* Qs = sm;          // [8][128][8]
    uint32_t* Ks = sm + 8192;
    const int tid = threadIdx.x;
    const int lane = tid & 31, warp = tid >> 5;
    const int wm = warp & 3, wn = warp >> 2;
    const int g = lane >> 2, tig = lane & 3;
    const int bh = blockIdx.z;
    const int b = bh / HH, h = bh % HH;
    const int t0 = blockIdx.y * 128, s0 = blockIdx.x * 128;

    #pragma unroll
    for (int i = 0; i < 8; i++) {
        int f = tid + (i << 8);
        int r = f >> 4;
        int c4 = (f & 15) << 2;
        int bse = ((c4 >> 3) << 10) + (r << 3) + ((c4 >> 2) & 1);
        float4 q4 = *(const float4*)(Q + ((size_t)(t0 + r) * BB + b) * DD + h * HDD + c4);
        Qs[bse + 0] = f2tf32(q4.x); Qs[bse + 2] = f2tf32(q4.y);
        Qs[bse + 4] = f2tf32(q4.z); Qs[bse + 6] = f2tf32(q4.w);
        float4 k4 = *(const float4*)(Kk + ((size_t)(s0 + r) * BB + b) * DD + h * HDD + c4);
        Ks[bse + 0] = f2tf32(k4.x); Ks[bse + 2] = f2tf32(k4.y);
        Ks[bse + 4] = f2tf32(k4.z); Ks[bse + 6] = f2tf32(k4.w);
    }
    __syncthreads();

    float d[2][8][4];
    #pragma unroll
    for (int mt = 0; mt < 2; mt++)
        #pragma unroll
        for (int nt = 0; nt < 8; nt++)
            #pragma unroll
            for (int i = 0; i < 4; i++) d[mt][nt][i] = 0.f;

    const int ar0 = (wm * 32 + g) * 8 + tig * 2;
    const int bc0 = (wn * 64 + g) * 8 + tig * 2;
    #pragma unroll
    for (int ks = 0; ks < 8; ks++) {
        int ab = (ks << 10);
        uint2 a00 = *(const uint2*)&Qs[ab + ar0];
        uint2 a01 = *(const uint2*)&Qs[ab + ar0 + 64];
        uint2 a10 = *(const uint2*)&Qs[ab + ar0 + 128];
        uint2 a11 = *(const uint2*)&Qs[ab + ar0 + 192];
        uint32_t af0[4] = {a00.x, a01.x, a00.y, a01.y};
        uint32_t af1[4] = {a10.x, a11.x, a10.y, a11.y};
        #pragma unroll
        for (int nt = 0; nt < 8; nt++) {
            uint2 bb = *(const uint2*)&Ks[ab + bc0 + nt * 64];
            mma_tf32(d[0][nt], af0, bb.x, bb.y);
            mma_tf32(d[1][nt], af1, bb.x, bb.y);
        }
    }

    #pragma unroll
    for (int mt = 0; mt < 2; mt++) {
        int t = t0 + wm * 32 + mt * 16 + g;
        #pragma unroll
        for (int nt = 0; nt < 8; nt++) {
            int s = s0 + wn * 64 + nt * 8 + tig * 2;
            float m00 = 0.f, m01 = 0.f, m10 = 0.f, m11 = 0.f;
            if (mask) {
                m00 = mask[(size_t)t * TT + s];       m01 = mask[(size_t)t * TT + s + 1];
                m10 = mask[(size_t)(t + 8) * TT + s]; m11 = mask[(size_t)(t + 8) * TT + s + 1];
            }
            float* p0 = Sc + ((size_t)bh * TT + t) * SSZ + s;
            float* p1 = Sc + ((size_t)bh * TT + t + 8) * SSZ + s;
            *(float2*)p0 = make_float2(d[mt][nt][0] * scale + m00, d[mt][nt][1] * scale + m01);
            *(float2*)p1 = make_float2(d[mt][nt][2] * scale + m10, d[mt][nt][3] * scale + m11);
        }
    }
}

// =====================================================================
// TF32 ctx: 128(m) x 64(n) x K=1024, double-buffered.
// A stage [4][128][8]=4096 words; W stage [4][64 x stride10]=2560 words.
// =====================================================================
#define CTX_STAGE 6656
__global__ __launch_bounds__(256) void ctx_tf32_kernel(
    const float* __restrict__ P, const float* __restrict__ V,
    float* __restrict__ ctx, float* __restrict__ attn)
{
    extern __shared__ uint32_t sm[];
    const int tid = threadIdx.x;
    const int lane = tid & 31, warp = tid >> 5;
    const int wm = warp & 3, wn = warp >> 2;
    const int g = lane >> 2, tig = lane & 3;
    const int bh = blockIdx.y;
    const int b = bh / HH, h = bh % HH;
    const int t0 = blockIdx.x * 128;
    const float* Pb = P + (size_t)bh * TT * SSZ;

    float d[2][4][4];
    #pragma unroll
    for (int mt = 0; mt < 2; mt++)
        #pragma unroll
        for (int nt = 0; nt < 4; nt++)
            #pragma unroll
            for (int i = 0; i < 4; i++) d[mt][nt][i] = 0.f;

    float4 pReg[4], vReg[2];
    auto load_regs = [&](int k0) {
        #pragma unroll
        for (int i = 0; i < 4; i++) {
            int f = tid + (i << 8);
            int r = f >> 3;
            int c4 = (f & 7) << 2;
            pReg[i] = *(const float4*)(Pb + (size_t)(t0 + r) * SSZ + k0 + c4);
        }
        #pragma unroll
        for (int i = 0; i < 2; i++) {
            int f = tid + (i << 8);
            int kr = f >> 4;
            int n4 = (f & 15) << 2;
            vReg[i] = *(const float4*)(V + ((size_t)(k0 + kr) * BB + b) * DD + h * HDD + n4);
        }
    };
    auto store_smem = [&](uint32_t* Ab, uint32_t* Wb) {
        #pragma unroll
        for (int i = 0; i < 4; i++) {
            int f = tid + (i << 8);
            int r = f >> 3;
            int c4 = (f & 7) << 2;
            int bse = ((c4 >> 3) << 10) + (r << 3) + ((c4 >> 2) & 1);
            Ab[bse + 0] = f2tf32(pReg[i].x);
            Ab[bse + 2] = f2tf32(pReg[i].y);
            Ab[bse + 4] = f2tf32(pReg[i].z);
            Ab[bse + 6] = f2tf32(pReg[i].w);
        }
        #pragma unroll
        for (int i = 0; i < 2; i++) {
            int f = tid + (i << 8);
            int kr = f >> 4;
            int n4 = (f & 15) << 2;
            int bse = (kr >> 3) * 640 + ((kr & 3) << 1) + ((kr >> 2) & 1);
            Wb[bse + (n4 + 0) * 10] = f2tf32(vReg[i].x);
            Wb[bse + (n4 + 1) * 10] = f2tf32(vReg[i].y);
            Wb[bse + (n4 + 2) * 10] = f2tf32(vReg[i].z);
            Wb[bse + (n4 + 3) * 10] = f2tf32(vReg[i].w);
        }
    };

    const int ar0 = (wm * 32 + g) * 8 + tig * 2;
    const int bc0 = (wn * 32 + g) * 10 + tig * 2;
    auto mma_stage = [&](const uint32_t* Ab, const uint32_t* Wb) {
        #pragma unroll
        for (int ks = 0; ks < 4; ks++) {
            int aoff = (ks << 10);
            int woff = ks * 640;
            uint2 a00 = *(const uint2*)&Ab[aoff + ar0];
            uint2 a01 = *(const uint2*)&Ab[aoff + ar0 + 64];
            uint2 a10 = *(const uint2*)&Ab[aoff + ar0 + 128];
            uint2 a11 = *(const uint2*)&Ab[aoff + ar0 + 192];
            uint32_t af0[4] = {a00.x, a01.x, a00.y, a01.y};
            uint32_t af1[4] = {a10.x, a11.x, a10.y, a11.y};
            #pragma unroll
            for (int nt = 0; nt < 4; nt++) {
                uint2 bb = *(const uint2*)&Wb[woff + bc0 + nt * 80];
                mma_tf32(d[0][nt], af0, bb.x, bb.y);
                mma_tf32(d[1][nt], af1, bb.x, bb.y);
            }
        }
    };

    load_regs(0);
    store_smem(sm, sm + 4096);
    __syncthreads();
    int stage = 0;
    for (int k0 = 0; k0 < SSZ; k0 += 32) {
        bool nxt = (k0 + 32) < SSZ;
        if (nxt) load_regs(k0 + 32);
        uint32_t* base = sm + stage * CTX_STAGE;
        mma_stage(base, base + 4096);
        if (nxt) {
            int ns = stage ^ 1;
            uint32_t* nb = sm + ns * CTX_STAGE;
            store_smem(nb, nb + 4096);
            __syncthreads();
            stage = ns;
        }
    }

    #pragma unroll
    for (int mt = 0; mt < 2; mt++) {
        int t = t0 + wm * 32 + mt * 16 + g;
        #pragma unroll
        for (int nt = 0; nt < 4; nt++) {
            int hd = wn * 32 + nt * 8 + tig * 2;
            float2 v0 = make_float2(d[mt][nt][0], d[mt][nt][1]);
            float2 v1 = make_float2(d[mt][nt][2], d[mt][nt][3]);
            *(float2*)(ctx + ((size_t)t * BB + b) * DD + h * HDD + hd)       = v0;
            *(float2*)(ctx + ((size_t)(t + 8) * BB + b) * DD + h * HDD + hd) = v1;
            if (attn) {
                *(float2*)(attn + (((size_t)h * BB + b) * TT + t) * HDD + hd)     = v0;
                *(float2*)(attn + (((size_t)h * BB + b) * TT + t + 8) * HDD + hd) = v1;
            }
        }
    }
}

// ---------------- softmax over last dim (1024), one block per row
__global__ __launch_bounds__(256) void softmax_kernel(float* __restrict__ Sc) {
    float* p = Sc + (size_t)blockIdx.x * SSZ;
    int tid = threadIdx.x;
    float4 v = *(float4*)(p + tid * 4);
    float m = fmaxf(fmaxf(v.x, v.y), fmaxf(v.z, v.w));
    m = block_max(m);
    float e0 = __expf(v.x - m), e1 = __expf(v.y - m);
    float e2 = __expf(v.z - m), e3 = __expf(v.w - m);
    float s = block_sum(e0 + e1 + e2 + e3);
    float inv = 1.f / s;
    float4 o; o.x = e0 * inv; o.y = e1 * inv; o.z = e2 * inv; o.w = e3 * inv;
    *(float4*)(p + tid * 4) = o;
}

// ---------------- fused residual add + layernorm
__global__ __launch_bounds__(256) void add_ln_kernel(
    const float* __restrict__ a, const float* __restrict__ r,
    const float* __restrict__ g, const float* __restrict__ be,
    float* __restrict__ o)
{
    size_t row = blockIdx.x;
    int tid = threadIdx.x;
    float4 va = *(const float4*)(a + row * DD + tid * 4);
    float4 vr = *(const float4*)(r + row * DD + tid * 4);
    float x0 = va.x + vr.x, x1 = va.y + vr.y, x2 = va.z + vr.z, x3 = va.w + vr.w;
    float s  = block_sum(x0 + x1 + x2 + x3);
    float mu = s * (1.f / DD);
    float d0 = x0 - mu, d1 = x1 - mu, d2 = x2 - mu, d3 = x3 - mu;
    float sq = block_sum(d0 * d0 + d1 * d1 + d2 * d2 + d3 * d3);
    float inv = rsqrtf(sq * (1.f / DD) + 1e-5f);
    float4 vg = *(const float4*)(g + tid * 4);
    float4 vb = *(const float4*)(be + tid * 4);
    float4 out;
    out.x = d0 * inv * vg.x + vb.x;
    out.y = d1 * inv * vg.y + vb.y;
    out.z = d2 * inv * vg.z + vb.z;
    out.w = d3 * inv * vg.w + vb.w;
    *(float4*)(o + row * DD + tid * 4) = out;
}

// ---------------- host launch ----------------
extern "C" void kernel_launch(void* const* d_in, const int* in_sizes, int n_in,
                              void* d_out, int out_size)
{
    const float* state = (const float*)d_in[0];
    const float* enc   = (const float*)d_in[1];
    const float* amask = (const float*)d_in[2];
    const int* spad = (const int*)d_in[3];
    const int* epad = (const int*)d_in[4];
    const float *saWq = (const float*)d_in[5],  *sabq = (const float*)d_in[6];
    const float *saWk = (const float*)d_in[7],  *sabk = (const float*)d_in[8];
    const float *saWv = (const float*)d_in[9],  *sabv = (const float*)d_in[10];
    const float *saWo = (const float*)d_in[11], *sabo = (const float*)d_in[12];
    const float *eaWq = (const float*)d_in[13], *eabq = (const float*)d_in[14];
    const float *eaWk = (const float*)d_in[15], *eabk = (const float*)d_in[16];
    const float *eaWv = (const float*)d_in[17], *eabv = (const float*)d_in[18];
    const float *eaWo = (const float*)d_in[19], *eabo = (const float*)d_in[20];
    const float *ln1g = (const float*)d_in[21], *ln1b = (const float*)d_in[22];
    const float *ln2g = (const float*)d_in[23], *ln2b = (const float*)d_in[24];
    const float *ln3g = (const float*)d_in[25], *ln3b = (const float*)d_in[26];
    const float *fc1W = (const float*)d_in[27], *fc1b = (const float*)d_in[28];
    const float *fc2W = (const float*)d_in[29], *fc2b = (const float*)d_in[30];

    float *q, *k, *v, *ctx, *tmp, *x1, *x2, *ffn, *sc, *rss, *rse;
    cudaGetSymbolAddress((void**)&q,   g_q);
    cudaGetSymbolAddress((void**)&k,   g_k);
    cudaGetSymbolAddress((void**)&v,   g_v);
    cudaGetSymbolAddress((void**)&ctx, g_ctx);
    cudaGetSymbolAddress((void**)&tmp, g_tmp);
    cudaGetSymbolAddress((void**)&x1,  g_x1);
    cudaGetSymbolAddress((void**)&x2,  g_x2);
    cudaGetSymbolAddress((void**)&ffn, g_ffn);
    cudaGetSymbolAddress((void**)&sc,  g_scores);
    cudaGetSymbolAddress((void**)&rss, g_rs_self);
    cudaGetSymbolAddress((void**)&rse, g_rs_enc);

    cudaFuncSetAttribute(gemm_tf32_kernel,   cudaFuncAttributeMaxDynamicSharedMemorySize, 65536);
    cudaFuncSetAttribute(scores_tf32_kernel, cudaFuncAttributeMaxDynamicSharedMemorySize, 65536);
    cudaFuncSetAttribute(ctx_tf32_kernel,    cudaFuncAttributeMaxDynamicSharedMemorySize, 2 * CTX_STAGE * 4);

    float* outx = (float*)d_out;
    float* outa = outx + (size_t)MM * DD;
    const float scale = 0.125f;

    expand_mask_kernel<<<(MM + 255) / 256, 256>>>(spad, rss, TT);
    expand_mask_kernel<<<(MM + 255) / 256, 256>>>(epad, rse, SSZ);

    const int GSM = 65536;
    const int CSM = 2 * CTX_STAGE * 4;
    dim3 gQKV(DD / 128, MM / 128, 3);
    dim3 gKV(DD / 128, MM / 128, 2);
    dim3 gP(DD / 128, MM / 128, 1);
    dim3 gF1(FFND / 128, MM / 128, 1);
    dim3 gSc(SSZ / 128, TT / 128, BB * HH);
    dim3 gCtx(TT / 128, BB * HH);

    GemmSet dummy = {nullptr, nullptr, nullptr, nullptr};

    // ---- self-attention ----
    {
        GemmSet s0 = {saWq, sabq, nullptr, q};
        GemmSet s1 = {saWk, sabk, rss,     k};
        GemmSet s2 = {saWv, sabv, nullptr, v};
        gemm_tf32_kernel<<<gQKV, 256, GSM>>>(state, s0, s1, s2, MM, DD, DD, 0);
    }
    scores_tf32_kernel<<<gSc, 256, GSM>>>(q, k, amask, sc, scale);
    softmax_kernel<<<BB * HH * TT, 256>>>(sc);
    ctx_tf32_kernel<<<gCtx, 256, CSM>>>(sc, v, ctx, nullptr);
    {
        GemmSet s0 = {saWo, sabo, nullptr, tmp};
        gemm_tf32_kernel<<<gP, 256, GSM>>>(ctx, s0, dummy, dummy, MM, DD, DD, 0);
    }
    add_ln_kernel<<<MM, 256>>>(tmp, state, ln1g, ln1b, x1);

    // ---- encoder-decoder attention ----
    {
        GemmSet s0 = {eaWq, eabq, nullptr, q};
        gemm_tf32_kernel<<<gP, 256, GSM>>>(x1, s0, dummy, dummy, MM, DD, DD, 0);
    }
    {
        GemmSet s0 = {eaWk, eabk, rse,     k};
        GemmSet s1 = {eaWv, eabv, nullptr, v};
        gemm_tf32_kernel<<<gKV, 256, GSM>>>(enc, s0, s1, dummy, MM, DD, DD, 0);
    }
    scores_tf32_kernel<<<gSc, 256, GSM>>>(q, k, nullptr, sc, scale);
    softmax_kernel<<<BB * HH * TT, 256>>>(sc);
    ctx_tf32_kernel<<<gCtx, 256, CSM>>>(sc, v, ctx, outa);
    {
        GemmSet s0 = {eaWo, eabo, nullptr, tmp};
        gemm_tf32_kernel<<<gP, 256, GSM>>>(ctx, s0, dummy, dummy, MM, DD, DD, 0);
    }
    add_ln_kernel<<<MM, 256>>>(tmp, x1, ln2g, ln2b, x2);

    // ---- FFN ----
    {
        GemmSet s0 = {fc1W, fc1b, nullptr, ffn};
        gemm_tf32_kernel<<<gF1, 256, GSM>>>(x2, s0, dummy, dummy, MM, FFND, DD, 1);
    }
    {
        GemmSet s0 = {fc2W, fc2b, nullptr, tmp};
        gemm_tf32_kernel<<<gP, 256, GSM>>>(ffn, s0, dummy, dummy, MM, DD, FFND, 0);
    }
    add_ln_kernel<<<MM, 256>>>(tmp, x2, ln3g, ln3b, outx);
}

// round 5
// speedup vs baseline: 1.1191x; 1.1191x over previous
#include <cuda_runtime.h>
#include <math.h>
#include <stdint.h>

#define TT   1024
#define SSZ  1024
#define BB   4
#define DD   1024
#define HH   16
#define HDD  64
#define FFND 4096
#define MM   (TT*BB)

// ---------------- scratch (device globals; no allocs allowed) ----------------
__device__ float g_q[MM*DD];
__device__ float g_k[MM*DD];
__device__ float g_v[MM*DD];
__device__ float g_ctx[MM*DD];
__device__ float g_tmp[MM*DD];
__device__ float g_x1[MM*DD];
__device__ float g_x2[MM*DD];
__device__ float g_ffn[(size_t)MM*FFND];
__device__ float g_rs_self[MM];
__device__ float g_rs_enc[MM];

// ---------------- helpers ----------------
__device__ __forceinline__ float block_sum(float v) {
    __shared__ float sh[8];
    __shared__ float res;
    int lane = threadIdx.x & 31, w = threadIdx.x >> 5;
    #pragma unroll
    for (int o = 16; o > 0; o >>= 1) v += __shfl_xor_sync(0xffffffffu, v, o);
    __syncthreads();
    if (lane == 0) sh[w] = v;
    __syncthreads();
    if (threadIdx.x == 0) {
        float t = 0.f;
        #pragma unroll
        for (int i = 0; i < 8; i++) t += sh[i];
        res = t;
    }
    __syncthreads();
    return res;
}

__device__ __forceinline__ uint32_t f2tf32(float x) {
    uint32_t u;
    asm("cvt.rna.tf32.f32 %0, %1;" : "=r"(u) : "f"(x));
    return u;
}

__device__ __forceinline__ void mma_tf32(float* d, const uint32_t* a, uint32_t b0, uint32_t b1) {
    asm volatile(
        "mma.sync.aligned.m16n8k8.row.col.f32.tf32.tf32.f32 "
        "{%0,%1,%2,%3}, {%4,%5,%6,%7}, {%8,%9}, {%0,%1,%2,%3};"
        : "+f"(d[0]), "+f"(d[1]), "+f"(d[2]), "+f"(d[3])
        : "r"(a[0]), "r"(a[1]), "r"(a[2]), "r"(a[3]), "r"(b0), "r"(b1));
}

__global__ void expand_mask_kernel(const int* __restrict__ mask,
                                   float* __restrict__ rowscale, int L) {
    int r = blockIdx.x * blockDim.x + threadIdx.x;
    if (r < L * BB) {
        int pos = r / BB, b = r % BB;
        rowscale[r] = mask[b * L + pos] ? 0.f : 1.f;
    }
}

// =====================================================================
// TF32 GEMM: C[M,N] = A[M,K] @ W[N,K]^T + bias. 128x128x32 tile, 256thr,
// double-buffered packed smem (LDS.64 fragment loads). smem 64KB dyn.
// =====================================================================
__global__ __launch_bounds__(256) void gemm_tf32_kernel(
    const float* __restrict__ A, const float* __restrict__ W,
    const float* __restrict__ bias, const float* __restrict__ rowscale,
    float* __restrict__ C, int M, int N, int K, int relu)
{
    extern __shared__ uint32_t sm[];
    const int tid = threadIdx.x;
    const int lane = tid & 31, warp = tid >> 5;
    const int wm = warp & 3, wn = warp >> 2;
    const int g = lane >> 2, tig = lane & 3;
    const int bx = blockIdx.x, by = blockIdx.y;

    float d[2][8][4];
    #pragma unroll
    for (int mt = 0; mt < 2; mt++)
        #pragma unroll
        for (int nt = 0; nt < 8; nt++)
            #pragma unroll
            for (int i = 0; i < 4; i++) d[mt][nt][i] = 0.f;

    float4 aReg[4], wReg[4];
    float ascale[4];
    int arow[4], wrow[4], sbase[4], colof[4];
    #pragma unroll
    for (int i = 0; i < 4; i++) {
        int f = tid + (i << 8);
        int r = f >> 3;
        int c4 = (f & 7) << 2;
        arow[i] = by * 128 + r;
        wrow[i] = bx * 128 + r;
        colof[i] = c4;
        sbase[i] = ((c4 >> 3) << 10) + (r << 3) + ((c4 >> 2) & 1);
        ascale[i] = rowscale ? rowscale[arow[i]] : 1.f;
    }

    auto load_regs = [&](int k0) {
        #pragma unroll
        for (int i = 0; i < 4; i++) {
            aReg[i] = *(const float4*)(A + (size_t)arow[i] * K + k0 + colof[i]);
            wReg[i] = *(const float4*)(W + (size_t)wrow[i] * K + k0 + colof[i]);
        }
    };
    auto store_smem = [&](uint32_t* Ab, uint32_t* Wb) {
        #pragma unroll
        for (int i = 0; i < 4; i++) {
            int bse = sbase[i];
            float s = ascale[i];
            Ab[bse + 0] = f2tf32(aReg[i].x * s);
            Ab[bse + 2] = f2tf32(aReg[i].y * s);
            Ab[bse + 4] = f2tf32(aReg[i].z * s);
            Ab[bse + 6] = f2tf32(aReg[i].w * s);
            Wb[bse + 0] = f2tf32(wReg[i].x);
            Wb[bse + 2] = f2tf32(wReg[i].y);
            Wb[bse + 4] = f2tf32(wReg[i].z);
            Wb[bse + 6] = f2tf32(wReg[i].w);
        }
    };

    const int ar0 = (wm * 32 + g) * 8 + tig * 2;
    const int bc0 = (wn * 64 + g) * 8 + tig * 2;

    auto mma_stage = [&](const uint32_t* Ab, const uint32_t* Wb) {
        #pragma unroll
        for (int ks = 0; ks < 4; ks++) {
            int ab = (ks << 10);
            uint2 a00 = *(const uint2*)&Ab[ab + ar0];
            uint2 a01 = *(const uint2*)&Ab[ab + ar0 + 64];
            uint2 a10 = *(const uint2*)&Ab[ab + ar0 + 128];
            uint2 a11 = *(const uint2*)&Ab[ab + ar0 + 192];
            uint32_t af0[4] = {a00.x, a01.x, a00.y, a01.y};
            uint32_t af1[4] = {a10.x, a11.x, a10.y, a11.y};
            #pragma unroll
            for (int nt = 0; nt < 8; nt++) {
                uint2 bb = *(const uint2*)&Wb[ab + bc0 + nt * 64];
                mma_tf32(d[0][nt], af0, bb.x, bb.y);
                mma_tf32(d[1][nt], af1, bb.x, bb.y);
            }
        }
    };

    load_regs(0);
    store_smem(sm, sm + 4096);
    __syncthreads();
    int stage = 0;
    for (int k0 = 0; k0 < K; k0 += 32) {
        bool nxt = (k0 + 32) < K;
        if (nxt) load_regs(k0 + 32);
        uint32_t* base = sm + stage * 8192;
        mma_stage(base, base + 4096);
        if (nxt) {
            int ns = stage ^ 1;
            uint32_t* nb = sm + ns * 8192;
            store_smem(nb, nb + 4096);
            __syncthreads();
            stage = ns;
        }
    }

    #pragma unroll
    for (int mt = 0; mt < 2; mt++) {
        int row0 = by * 128 + wm * 32 + mt * 16 + g;
        #pragma unroll
        for (int nt = 0; nt < 8; nt++) {
            int col = bx * 128 + wn * 64 + nt * 8 + tig * 2;
            float b0 = bias[col], b1 = bias[col + 1];
            float v00 = d[mt][nt][0] + b0, v01 = d[mt][nt][1] + b1;
            float v10 = d[mt][nt][2] + b0, v11 = d[mt][nt][3] + b1;
            if (relu) {
                v00 = fmaxf(v00, 0.f); v01 = fmaxf(v01, 0.f);
                v10 = fmaxf(v10, 0.f); v11 = fmaxf(v11, 0.f);
            }
            *(float2*)(C + (size_t)row0 * N + col)       = make_float2(v00, v01);
            *(float2*)(C + (size_t)(row0 + 8) * N + col) = make_float2(v10, v11);
        }
    }
}

// =====================================================================
// Fused flash attention (tf32). grid (T/128, B*H), 256 thr (8 warps,
// each owning 16 t-rows). Q tile resident; loop over 128-wide s-tiles:
// S = QK^T (MMA) -> scale (+ mask on diagonal tile if causal) -> online
// softmax in registers -> P via warp-private smem -> O += P@V (MMA).
// Writes ctx [t*B+b][h*64+hd] and optional attn [h,b,t,hd] = ctx.
// smem words: Q 8192 | K 8192 | V 10240 | P 8x2048  => 172KB.
// =====================================================================
#define FQ 0
#define FK 8192
#define FV 16384
#define FP 26624
#define FL_SMEM_WORDS 43008

__global__ __launch_bounds__(256) void flash_tf32_kernel(
    const float* __restrict__ Q, const float* __restrict__ Kk,
    const float* __restrict__ V, const float* __restrict__ mask,
    float* __restrict__ ctx, float* __restrict__ attn, int causal)
{
    extern __shared__ uint32_t sm[];
    uint32_t* Qs = sm + FQ;
    uint32_t* Ks = sm + FK;
    uint32_t* Vs = sm + FV;
    const int tid = threadIdx.x;
    const int lane = tid & 31, warp = tid >> 5;
    const int g = lane >> 2, tig = lane & 3;
    const int bh = blockIdx.y;
    const int b = bh / HH, h = bh % HH;
    const int t0 = blockIdx.x * 128;
    const int wr0 = warp * 16;
    uint32_t* Pw = sm + FP + warp * 2048;

    // load Q tile (128 x 64) into packed A layout
    #pragma unroll
    for (int i = 0; i < 8; i++) {
        int f = tid + (i << 8);
        int r = f >> 4;
        int c4 = (f & 15) << 2;
        int bse = ((c4 >> 3) << 10) + (r << 3) + ((c4 >> 2) & 1);
        float4 q4 = *(const float4*)(Q + ((size_t)(t0 + r) * BB + b) * DD + h * HDD + c4);
        Qs[bse + 0] = f2tf32(q4.x); Qs[bse + 2] = f2tf32(q4.y);
        Qs[bse + 4] = f2tf32(q4.z); Qs[bse + 6] = f2tf32(q4.w);
    }

    float mA = -1e30f, mB = -1e30f, lA = 0.f, lB = 0.f;
    float o[8][4];
    #pragma unroll
    for (int nt = 0; nt < 8; nt++)
        #pragma unroll
        for (int i = 0; i < 4; i++) o[nt][i] = 0.f;

    const int pe = ((tig * 2) & 3) * 2 + (tig >> 1);   // {0,4,1,5}
    const int n_stiles = causal ? (blockIdx.x + 1) : (SSZ / 128);

    for (int is = 0; is < n_stiles; is++) {
        int s0 = is * 128;
        __syncthreads();   // protect K/V smem (and first-pass Q visibility)

        // K tile (128 x 64) packed B layout; V tile transposed [n][k] stride-10
        #pragma unroll
        for (int i = 0; i < 8; i++) {
            int f = tid + (i << 8);
            int r = f >> 4;
            int c4 = (f & 15) << 2;
            int bse = ((c4 >> 3) << 10) + (r << 3) + ((c4 >> 2) & 1);
            float4 k4 = *(const float4*)(Kk + ((size_t)(s0 + r) * BB + b) * DD + h * HDD + c4);
            Ks[bse + 0] = f2tf32(k4.x); Ks[bse + 2] = f2tf32(k4.y);
            Ks[bse + 4] = f2tf32(k4.z); Ks[bse + 6] = f2tf32(k4.w);
            float4 v4 = *(const float4*)(V + ((size_t)(s0 + r) * BB + b) * DD + h * HDD + c4);
            int vb = ((r >> 3) * 640) + ((r & 3) << 1) + ((r >> 2) & 1);
            Vs[vb + (c4 + 0) * 10] = f2tf32(v4.x);
            Vs[vb + (c4 + 1) * 10] = f2tf32(v4.y);
            Vs[vb + (c4 + 2) * 10] = f2tf32(v4.z);
            Vs[vb + (c4 + 3) * 10] = f2tf32(v4.w);
        }
        __syncthreads();

        // ---- S = Q @ K^T : per-warp 16 x 128 ----
        float s[16][4];
        #pragma unroll
        for (int nt = 0; nt < 16; nt++)
            #pragma unroll
            for (int i = 0; i < 4; i++) s[nt][i] = 0.f;

        #pragma unroll
        for (int ks = 0; ks < 8; ks++) {
            int ab = ks << 10;
            uint2 a0 = *(const uint2*)&Qs[ab + (wr0 + g) * 8 + tig * 2];
            uint2 a1 = *(const uint2*)&Qs[ab + (wr0 + 8 + g) * 8 + tig * 2];
            uint32_t af[4] = {a0.x, a1.x, a0.y, a1.y};
            #pragma unroll
            for (int nt = 0; nt < 16; nt++) {
                uint2 bb = *(const uint2*)&Ks[ab + (nt * 8 + g) * 8 + tig * 2];
                mma_tf32(s[nt], af, bb.x, bb.y);
            }
        }

        // scale + (diagonal) mask
        const float scale = 0.125f;
        if (causal && is == blockIdx.x) {
            int tAr = t0 + wr0 + g, tBr = tAr + 8;
            #pragma unroll
            for (int nt = 0; nt < 16; nt++) {
                int c = s0 + nt * 8 + tig * 2;
                s[nt][0] = s[nt][0] * scale + mask[(size_t)tAr * TT + c];
                s[nt][1] = s[nt][1] * scale + mask[(size_t)tAr * TT + c + 1];
                s[nt][2] = s[nt][2] * scale + mask[(size_t)tBr * TT + c];
                s[nt][3] = s[nt][3] * scale + mask[(size_t)tBr * TT + c + 1];
            }
        } else {
            #pragma unroll
            for (int nt = 0; nt < 16; nt++)
                #pragma unroll
                for (int i = 0; i < 4; i++) s[nt][i] *= scale;
        }

        // ---- online softmax ----
        float mtA = -1e30f, mtB = -1e30f;
        #pragma unroll
        for (int nt = 0; nt < 16; nt++) {
            mtA = fmaxf(mtA, fmaxf(s[nt][0], s[nt][1]));
            mtB = fmaxf(mtB, fmaxf(s[nt][2], s[nt][3]));
        }
        mtA = fmaxf(mtA, __shfl_xor_sync(0xffffffffu, mtA, 1));
        mtA = fmaxf(mtA, __shfl_xor_sync(0xffffffffu, mtA, 2));
        mtB = fmaxf(mtB, __shfl_xor_sync(0xffffffffu, mtB, 1));
        mtB = fmaxf(mtB, __shfl_xor_sync(0xffffffffu, mtB, 2));

        float mnA = fmaxf(mA, mtA), mnB = fmaxf(mB, mtB);
        float alA = __expf(mA - mnA), alB = __expf(mB - mnB);
        float rsA = 0.f, rsB = 0.f;
        #pragma unroll
        for (int nt = 0; nt < 16; nt++) {
            s[nt][0] = __expf(s[nt][0] - mnA);
            s[nt][1] = __expf(s[nt][1] - mnA);
            s[nt][2] = __expf(s[nt][2] - mnB);
            s[nt][3] = __expf(s[nt][3] - mnB);
            rsA += s[nt][0] + s[nt][1];
            rsB += s[nt][2] + s[nt][3];
        }
        rsA += __shfl_xor_sync(0xffffffffu, rsA, 1);
        rsA += __shfl_xor_sync(0xffffffffu, rsA, 2);
        rsB += __shfl_xor_sync(0xffffffffu, rsB, 1);
        rsB += __shfl_xor_sync(0xffffffffu, rsB, 2);
        lA = lA * alA + rsA; mA = mnA;
        lB = lB * alB + rsB; mB = mnB;

        #pragma unroll
        for (int nt = 0; nt < 8; nt++) {
            o[nt][0] *= alA; o[nt][1] *= alA;
            o[nt][2] *= alB; o[nt][3] *= alB;
        }

        // ---- P to warp-private smem (packed A layout, k = s-col) ----
        __syncwarp();
        #pragma unroll
        for (int nt = 0; nt < 16; nt++) {
            int base = (nt << 7) + g * 8 + pe;
            Pw[base]            = f2tf32(s[nt][0]);
            Pw[base + 2]        = f2tf32(s[nt][1]);
            Pw[base + 64]       = f2tf32(s[nt][2]);
            Pw[base + 64 + 2]   = f2tf32(s[nt][3]);
        }
        __syncwarp();

        // ---- O += P @ V ----
        #pragma unroll
        for (int ks = 0; ks < 16; ks++) {
            uint2 a0 = *(const uint2*)&Pw[(ks << 7) + g * 8 + tig * 2];
            uint2 a1 = *(const uint2*)&Pw[(ks << 7) + (g + 8) * 8 + tig * 2];
            uint32_t af[4] = {a0.x, a1.x, a0.y, a1.y};
            #pragma unroll
            for (int nt = 0; nt < 8; nt++) {
                uint2 bb = *(const uint2*)&Vs[ks * 640 + (nt * 8 + g) * 10 + tig * 2];
                mma_tf32(o[nt], af, bb.x, bb.y);
            }
        }
    }

    // ---- epilogue ----
    float invA = 1.f / lA, invB = 1.f / lB;
    int tA = t0 + wr0 + g, tB = tA + 8;
    #pragma unroll
    for (int nt = 0; nt < 8; nt++) {
        int hd = nt * 8 + tig * 2;
        float2 vA = make_float2(o[nt][0] * invA, o[nt][1] * invA);
        float2 vB = make_float2(o[nt][2] * invB, o[nt][3] * invB);
        *(float2*)(ctx + ((size_t)tA * BB + b) * DD + h * HDD + hd) = vA;
        *(float2*)(ctx + ((size_t)tB * BB + b) * DD + h * HDD + hd) = vB;
        if (attn) {
            *(float2*)(attn + (((size_t)h * BB + b) * TT + tA) * HDD + hd) = vA;
            *(float2*)(attn + (((size_t)h * BB + b) * TT + tB) * HDD + hd) = vB;
        }
    }
}

// ---------------- fused residual add + layernorm
__global__ __launch_bounds__(256) void add_ln_kernel(
    const float* __restrict__ a, const float* __restrict__ r,
    const float* __restrict__ g, const float* __restrict__ be,
    float* __restrict__ o)
{
    size_t row = blockIdx.x;
    int tid = threadIdx.x;
    float4 va = *(const float4*)(a + row * DD + tid * 4);
    float4 vr = *(const float4*)(r + row * DD + tid * 4);
    float x0 = va.x + vr.x, x1 = va.y + vr.y, x2 = va.z + vr.z, x3 = va.w + vr.w;
    float s  = block_sum(x0 + x1 + x2 + x3);
    float mu = s * (1.f / DD);
    float d0 = x0 - mu, d1 = x1 - mu, d2 = x2 - mu, d3 = x3 - mu;
    float sq = block_sum(d0 * d0 + d1 * d1 + d2 * d2 + d3 * d3);
    float inv = rsqrtf(sq * (1.f / DD) + 1e-5f);
    float4 vg = *(const float4*)(g + tid * 4);
    float4 vb = *(const float4*)(be + tid * 4);
    float4 out;
    out.x = d0 * inv * vg.x + vb.x;
    out.y = d1 * inv * vg.y + vb.y;
    out.z = d2 * inv * vg.z + vb.z;
    out.w = d3 * inv * vg.w + vb.w;
    *(float4*)(o + row * DD + tid * 4) = out;
}

// ---------------- host launch ----------------
extern "C" void kernel_launch(void* const* d_in, const int* in_sizes, int n_in,
                              void* d_out, int out_size)
{
    const float* state = (const float*)d_in[0];
    const float* enc   = (const float*)d_in[1];
    const float* amask = (const float*)d_in[2];
    const int* spad = (const int*)d_in[3];
    const int* epad = (const int*)d_in[4];
    const float *saWq = (const float*)d_in[5],  *sabq = (const float*)d_in[6];
    const float *saWk = (const float*)d_in[7],  *sabk = (const float*)d_in[8];
    const float *saWv = (const float*)d_in[9],  *sabv = (const float*)d_in[10];
    const float *saWo = (const float*)d_in[11], *sabo = (const float*)d_in[12];
    const float *eaWq = (const float*)d_in[13], *eabq = (const float*)d_in[14];
    const float *eaWk = (const float*)d_in[15], *eabk = (const float*)d_in[16];
    const float *eaWv = (const float*)d_in[17], *eabv = (const float*)d_in[18];
    const float *eaWo = (const float*)d_in[19], *eabo = (const float*)d_in[20];
    const float *ln1g = (const float*)d_in[21], *ln1b = (const float*)d_in[22];
    const float *ln2g = (const float*)d_in[23], *ln2b = (const float*)d_in[24];
    const float *ln3g = (const float*)d_in[25], *ln3b = (const float*)d_in[26];
    const float *fc1W = (const float*)d_in[27], *fc1b = (const float*)d_in[28];
    const float *fc2W = (const float*)d_in[29], *fc2b = (const float*)d_in[30];

    float *q, *k, *v, *ctx, *tmp, *x1, *x2, *ffn, *rss, *rse;
    cudaGetSymbolAddress((void**)&q,   g_q);
    cudaGetSymbolAddress((void**)&k,   g_k);
    cudaGetSymbolAddress((void**)&v,   g_v);
    cudaGetSymbolAddress((void**)&ctx, g_ctx);
    cudaGetSymbolAddress((void**)&tmp, g_tmp);
    cudaGetSymbolAddress((void**)&x1,  g_x1);
    cudaGetSymbolAddress((void**)&x2,  g_x2);
    cudaGetSymbolAddress((void**)&ffn, g_ffn);
    cudaGetSymbolAddress((void**)&rss, g_rs_self);
    cudaGetSymbolAddress((void**)&rse, g_rs_enc);

    const int GSM = 65536;
    const int FSM = FL_SMEM_WORDS * 4;  // 172032
    cudaFuncSetAttribute(gemm_tf32_kernel,  cudaFuncAttributeMaxDynamicSharedMemorySize, GSM);
    cudaFuncSetAttribute(flash_tf32_kernel, cudaFuncAttributeMaxDynamicSharedMemorySize, FSM);

    float* outx = (float*)d_out;
    float* outa = outx + (size_t)MM * DD;

    expand_mask_kernel<<<(MM + 255) / 256, 256>>>(spad, rss, TT);
    expand_mask_kernel<<<(MM + 255) / 256, 256>>>(epad, rse, SSZ);

    dim3 gP(DD / 128, MM / 128);
    dim3 gF1(FFND / 128, MM / 128);
    dim3 gFl(TT / 128, BB * HH);

    // ---- self-attention ----
    gemm_tf32_kernel<<<gP, 256, GSM>>>(state, saWq, sabq, nullptr, q, MM, DD, DD, 0);
    gemm_tf32_kernel<<<gP, 256, GSM>>>(state, saWk, sabk, rss,     k, MM, DD, DD, 0);
    gemm_tf32_kernel<<<gP, 256, GSM>>>(state, saWv, sabv, nullptr, v, MM, DD, DD, 0);
    flash_tf32_kernel<<<gFl, 256, FSM>>>(q, k, v, amask, ctx, nullptr, 1);
    gemm_tf32_kernel<<<gP, 256, GSM>>>(ctx, saWo, sabo, nullptr, tmp, MM, DD, DD, 0);
    add_ln_kernel<<<MM, 256>>>(tmp, state, ln1g, ln1b, x1);

    // ---- encoder-decoder attention ----
    gemm_tf32_kernel<<<gP, 256, GSM>>>(x1,  eaWq, eabq, nullptr, q, MM, DD, DD, 0);
    gemm_tf32_kernel<<<gP, 256, GSM>>>(enc, eaWk, eabk, rse,     k, MM, DD, DD, 0);
    gemm_tf32_kernel<<<gP, 256, GSM>>>(enc, eaWv, eabv, nullptr, v, MM, DD, DD, 0);
    flash_tf32_kernel<<<gFl, 256, FSM>>>(q, k, v, nullptr, ctx, outa, 0);
    gemm_tf32_kernel<<<gP, 256, GSM>>>(ctx, eaWo, eabo, nullptr, tmp, MM, DD, DD, 0);
    add_ln_kernel<<<MM, 256>>>(tmp, x1, ln2g, ln2b, x2);

    // ---- FFN ----
    gemm_tf32_kernel<<<gF1, 256, GSM>>>(x2, fc1W, fc1b, nullptr, ffn, MM, FFND, DD, 1);
    gemm_tf32_kernel<<<gP, 256, GSM>>>(ffn, fc2W, fc2b, nullptr, tmp, MM, DD, FFND, 0);
    add_ln_kernel<<<MM, 256>>>(tmp, x2, ln3g, ln3b, outx);
}

// round 6
// speedup vs baseline: 1.1943x; 1.0671x over previous
#include <cuda_runtime.h>
#include <math.h>
#include <stdint.h>

#define TT   1024
#define SSZ  1024
#define BB   4
#define DD   1024
#define HH   16
#define HDD  64
#define FFND 4096
#define MM   (TT*BB)

// ---------------- scratch (device globals; no allocs allowed) ----------------
__device__ float g_q[MM*DD];
__device__ float g_k[MM*DD];
__device__ float g_v[MM*DD];
__device__ float g_ctx[MM*DD];
__device__ float g_tmp[MM*DD];
__device__ float g_x1[MM*DD];
__device__ float g_x2[MM*DD];
__device__ float g_ffn[(size_t)MM*FFND];
__device__ float g_rs_self[MM];
__device__ float g_rs_enc[MM];

// ---------------- helpers ----------------
__device__ __forceinline__ float block_sum(float v) {
    __shared__ float sh[8];
    __shared__ float res;
    int lane = threadIdx.x & 31, w = threadIdx.x >> 5;
    #pragma unroll
    for (int o = 16; o > 0; o >>= 1) v += __shfl_xor_sync(0xffffffffu, v, o);
    __syncthreads();
    if (lane == 0) sh[w] = v;
    __syncthreads();
    if (threadIdx.x == 0) {
        float t = 0.f;
        #pragma unroll
        for (int i = 0; i < 8; i++) t += sh[i];
        res = t;
    }
    __syncthreads();
    return res;
}

__device__ __forceinline__ uint32_t f2tf32(float x) {
    uint32_t u;
    asm("cvt.rna.tf32.f32 %0, %1;" : "=r"(u) : "f"(x));
    return u;
}

__device__ __forceinline__ void mma_tf32(float* d, const uint32_t* a, uint32_t b0, uint32_t b1) {
    asm volatile(
        "mma.sync.aligned.m16n8k8.row.col.f32.tf32.tf32.f32 "
        "{%0,%1,%2,%3}, {%4,%5,%6,%7}, {%8,%9}, {%0,%1,%2,%3};"
        : "+f"(d[0]), "+f"(d[1]), "+f"(d[2]), "+f"(d[3])
        : "r"(a[0]), "r"(a[1]), "r"(a[2]), "r"(a[3]), "r"(b0), "r"(b1));
}

__global__ void expand_mask_kernel(const int* __restrict__ mask,
                                   float* __restrict__ rowscale, int L) {
    int r = blockIdx.x * blockDim.x + threadIdx.x;
    if (r < L * BB) {
        int pos = r / BB, b = r % BB;
        rowscale[r] = mask[b * L + pos] ? 0.f : 1.f;
    }
}

// =====================================================================
// TF32 GEMM: C[M,N] = A[M,K] @ W[N,K]^T + bias. 128x128x16 tile,
// 256 thr, 2 CTAs/SM, double-buffered packed smem (LDS.64 fragments).
// Dynamic smem = 2 stages * (2048 + 2048) words * 4B = 32KB.
// =====================================================================
__global__ __launch_bounds__(256, 2) void gemm_tf32_kernel(
    const float* __restrict__ A, const float* __restrict__ W,
    const float* __restrict__ bias, const float* __restrict__ rowscale,
    float* __restrict__ C, int M, int N, int K, int relu)
{
    extern __shared__ uint32_t sm[];
    const int tid = threadIdx.x;
    const int lane = tid & 31, warp = tid >> 5;
    const int wm = warp & 3, wn = warp >> 2;
    const int g = lane >> 2, tig = lane & 3;
    const int bx = blockIdx.x, by = blockIdx.y;

    float d[2][8][4];
    #pragma unroll
    for (int mt = 0; mt < 2; mt++)
        #pragma unroll
        for (int nt = 0; nt < 8; nt++)
            #pragma unroll
            for (int i = 0; i < 4; i++) d[mt][nt][i] = 0.f;

    // load mapping: 128 rows x 16 cols per matrix; thread f -> r=f>>2, c4=(f&3)*4
    float4 aReg[2], wReg[2];
    float ascale[2];
    int arow[2], wrow[2], sbase[2], colof[2];
    #pragma unroll
    for (int i = 0; i < 2; i++) {
        int f = tid + (i << 8);
        int r = f >> 2;
        int c4 = (f & 3) << 2;
        arow[i] = by * 128 + r;
        wrow[i] = bx * 128 + r;
        colof[i] = c4;
        sbase[i] = ((c4 >> 3) << 10) + (r << 3) + ((c4 >> 2) & 1);
        ascale[i] = rowscale ? rowscale[arow[i]] : 1.f;
    }

    auto load_regs = [&](int k0) {
        #pragma unroll
        for (int i = 0; i < 2; i++) {
            aReg[i] = *(const float4*)(A + (size_t)arow[i] * K + k0 + colof[i]);
            wReg[i] = *(const float4*)(W + (size_t)wrow[i] * K + k0 + colof[i]);
        }
    };
    auto store_smem = [&](uint32_t* Ab, uint32_t* Wb) {
        #pragma unroll
        for (int i = 0; i < 2; i++) {
            int bse = sbase[i];
            float s = ascale[i];
            Ab[bse + 0] = f2tf32(aReg[i].x * s);
            Ab[bse + 2] = f2tf32(aReg[i].y * s);
            Ab[bse + 4] = f2tf32(aReg[i].z * s);
            Ab[bse + 6] = f2tf32(aReg[i].w * s);
            Wb[bse + 0] = f2tf32(wReg[i].x);
            Wb[bse + 2] = f2tf32(wReg[i].y);
            Wb[bse + 4] = f2tf32(wReg[i].z);
            Wb[bse + 6] = f2tf32(wReg[i].w);
        }
    };

    const int ar0 = (wm * 32 + g) * 8 + tig * 2;
    const int bc0 = (wn * 64 + g) * 8 + tig * 2;

    auto mma_stage = [&](const uint32_t* Ab, const uint32_t* Wb) {
        #pragma unroll
        for (int ks = 0; ks < 2; ks++) {
            int ab = (ks << 10);
            uint2 a00 = *(const uint2*)&Ab[ab + ar0];
            uint2 a01 = *(const uint2*)&Ab[ab + ar0 + 64];
            uint2 a10 = *(const uint2*)&Ab[ab + ar0 + 128];
            uint2 a11 = *(const uint2*)&Ab[ab + ar0 + 192];
            uint32_t af0[4] = {a00.x, a01.x, a00.y, a01.y};
            uint32_t af1[4] = {a10.x, a11.x, a10.y, a11.y};
            #pragma unroll
            for (int nt = 0; nt < 8; nt++) {
                uint2 bb = *(const uint2*)&Wb[ab + bc0 + nt * 64];
                mma_tf32(d[0][nt], af0, bb.x, bb.y);
                mma_tf32(d[1][nt], af1, bb.x, bb.y);
            }
        }
    };

    uint32_t* const A0 = sm;
    uint32_t* const W0 = sm + 2048;
    uint32_t* const A1 = sm + 4096;
    uint32_t* const W1 = sm + 6144;

    load_regs(0);
    store_smem(A0, W0);
    __syncthreads();
    int stage = 0;
    for (int k0 = 0; k0 < K; k0 += 16) {
        bool nxt = (k0 + 16) < K;
        if (nxt) load_regs(k0 + 16);
        if (stage == 0) {
            mma_stage(A0, W0);
            if (nxt) { store_smem(A1, W1); __syncthreads(); stage = 1; }
        } else {
            mma_stage(A1, W1);
            if (nxt) { store_smem(A0, W0); __syncthreads(); stage = 0; }
        }
    }

    #pragma unroll
    for (int mt = 0; mt < 2; mt++) {
        int row0 = by * 128 + wm * 32 + mt * 16 + g;
        #pragma unroll
        for (int nt = 0; nt < 8; nt++) {
            int col = bx * 128 + wn * 64 + nt * 8 + tig * 2;
            float b0 = bias[col], b1 = bias[col + 1];
            float v00 = d[mt][nt][0] + b0, v01 = d[mt][nt][1] + b1;
            float v10 = d[mt][nt][2] + b0, v11 = d[mt][nt][3] + b1;
            if (relu) {
                v00 = fmaxf(v00, 0.f); v01 = fmaxf(v01, 0.f);
                v10 = fmaxf(v10, 0.f); v11 = fmaxf(v11, 0.f);
            }
            *(float2*)(C + (size_t)row0 * N + col)       = make_float2(v00, v01);
            *(float2*)(C + (size_t)(row0 + 8) * N + col) = make_float2(v10, v11);
        }
    }
}

// =====================================================================
// Fused flash attention (tf32) — unchanged from round 5.
// =====================================================================
#define FQ 0
#define FK 8192
#define FV 16384
#define FP 26624
#define FL_SMEM_WORDS 43008

__global__ __launch_bounds__(256) void flash_tf32_kernel(
    const float* __restrict__ Q, const float* __restrict__ Kk,
    const float* __restrict__ V, const float* __restrict__ mask,
    float* __restrict__ ctx, float* __restrict__ attn, int causal)
{
    extern __shared__ uint32_t sm[];
    uint32_t* Qs = sm + FQ;
    uint32_t* Ks = sm + FK;
    uint32_t* Vs = sm + FV;
    const int tid = threadIdx.x;
    const int lane = tid & 31, warp = tid >> 5;
    const int g = lane >> 2, tig = lane & 3;
    const int bh = blockIdx.y;
    const int b = bh / HH, h = bh % HH;
    const int t0 = blockIdx.x * 128;
    const int wr0 = warp * 16;
    uint32_t* Pw = sm + FP + warp * 2048;

    #pragma unroll
    for (int i = 0; i < 8; i++) {
        int f = tid + (i << 8);
        int r = f >> 4;
        int c4 = (f & 15) << 2;
        int bse = ((c4 >> 3) << 10) + (r << 3) + ((c4 >> 2) & 1);
        float4 q4 = *(const float4*)(Q + ((size_t)(t0 + r) * BB + b) * DD + h * HDD + c4);
        Qs[bse + 0] = f2tf32(q4.x); Qs[bse + 2] = f2tf32(q4.y);
        Qs[bse + 4] = f2tf32(q4.z); Qs[bse + 6] = f2tf32(q4.w);
    }

    float mA = -1e30f, mB = -1e30f, lA = 0.f, lB = 0.f;
    float o[8][4];
    #pragma unroll
    for (int nt = 0; nt < 8; nt++)
        #pragma unroll
        for (int i = 0; i < 4; i++) o[nt][i] = 0.f;

    const int pe = ((tig * 2) & 3) * 2 + (tig >> 1);
    const int n_stiles = causal ? (blockIdx.x + 1) : (SSZ / 128);

    for (int is = 0; is < n_stiles; is++) {
        int s0 = is * 128;
        __syncthreads();

        #pragma unroll
        for (int i = 0; i < 8; i++) {
            int f = tid + (i << 8);
            int r = f >> 4;
            int c4 = (f & 15) << 2;
            int bse = ((c4 >> 3) << 10) + (r << 3) + ((c4 >> 2) & 1);
            float4 k4 = *(const float4*)(Kk + ((size_t)(s0 + r) * BB + b) * DD + h * HDD + c4);
            Ks[bse + 0] = f2tf32(k4.x); Ks[bse + 2] = f2tf32(k4.y);
            Ks[bse + 4] = f2tf32(k4.z); Ks[bse + 6] = f2tf32(k4.w);
            float4 v4 = *(const float4*)(V + ((size_t)(s0 + r) * BB + b) * DD + h * HDD + c4);
            int vb = ((r >> 3) * 640) + ((r & 3) << 1) + ((r >> 2) & 1);
            Vs[vb + (c4 + 0) * 10] = f2tf32(v4.x);
            Vs[vb + (c4 + 1) * 10] = f2tf32(v4.y);
            Vs[vb + (c4 + 2) * 10] = f2tf32(v4.z);
            Vs[vb + (c4 + 3) * 10] = f2tf32(v4.w);
        }
        __syncthreads();

        float s[16][4];
        #pragma unroll
        for (int nt = 0; nt < 16; nt++)
            #pragma unroll
            for (int i = 0; i < 4; i++) s[nt][i] = 0.f;

        #pragma unroll
        for (int ks = 0; ks < 8; ks++) {
            int ab = ks << 10;
            uint2 a0 = *(const uint2*)&Qs[ab + (wr0 + g) * 8 + tig * 2];
            uint2 a1 = *(const uint2*)&Qs[ab + (wr0 + 8 + g) * 8 + tig * 2];
            uint32_t af[4] = {a0.x, a1.x, a0.y, a1.y};
            #pragma unroll
            for (int nt = 0; nt < 16; nt++) {
                uint2 bb = *(const uint2*)&Ks[ab + (nt * 8 + g) * 8 + tig * 2];
                mma_tf32(s[nt], af, bb.x, bb.y);
            }
        }

        const float scale = 0.125f;
        if (causal && is == blockIdx.x) {
            int tAr = t0 + wr0 + g, tBr = tAr + 8;
            #pragma unroll
            for (int nt = 0; nt < 16; nt++) {
                int c = s0 + nt * 8 + tig * 2;
                s[nt][0] = s[nt][0] * scale + mask[(size_t)tAr * TT + c];
                s[nt][1] = s[nt][1] * scale + mask[(size_t)tAr * TT + c + 1];
                s[nt][2] = s[nt][2] * scale + mask[(size_t)tBr * TT + c];
                s[nt][3] = s[nt][3] * scale + mask[(size_t)tBr * TT + c + 1];
            }
        } else {
            #pragma unroll
            for (int nt = 0; nt < 16; nt++)
                #pragma unroll
                for (int i = 0; i < 4; i++) s[nt][i] *= scale;
        }

        float mtA = -1e30f, mtB = -1e30f;
        #pragma unroll
        for (int nt = 0; nt < 16; nt++) {
            mtA = fmaxf(mtA, fmaxf(s[nt][0], s[nt][1]));
            mtB = fmaxf(mtB, fmaxf(s[nt][2], s[nt][3]));
        }
        mtA = fmaxf(mtA, __shfl_xor_sync(0xffffffffu, mtA, 1));
        mtA = fmaxf(mtA, __shfl_xor_sync(0xffffffffu, mtA, 2));
        mtB = fmaxf(mtB, __shfl_xor_sync(0xffffffffu, mtB, 1));
        mtB = fmaxf(mtB, __shfl_xor_sync(0xffffffffu, mtB, 2));

        float mnA = fmaxf(mA, mtA), mnB = fmaxf(mB, mtB);
        float alA = __expf(mA - mnA), alB = __expf(mB - mnB);
        float rsA = 0.f, rsB = 0.f;
        #pragma unroll
        for (int nt = 0; nt < 16; nt++) {
            s[nt][0] = __expf(s[nt][0] - mnA);
            s[nt][1] = __expf(s[nt][1] - mnA);
            s[nt][2] = __expf(s[nt][2] - mnB);
            s[nt][3] = __expf(s[nt][3] - mnB);
            rsA += s[nt][0] + s[nt][1];
            rsB += s[nt][2] + s[nt][3];
        }
        rsA += __shfl_xor_sync(0xffffffffu, rsA, 1);
        rsA += __shfl_xor_sync(0xffffffffu, rsA, 2);
        rsB += __shfl_xor_sync(0xffffffffu, rsB, 1);
        rsB += __shfl_xor_sync(0xffffffffu, rsB, 2);
        lA = lA * alA + rsA; mA = mnA;
        lB = lB * alB + rsB; mB = mnB;

        #pragma unroll
        for (int nt = 0; nt < 8; nt++) {
            o[nt][0] *= alA; o[nt][1] *= alA;
            o[nt][2] *= alB; o[nt][3] *= alB;
        }

        __syncwarp();
        #pragma unroll
        for (int nt = 0; nt < 16; nt++) {
            int base = (nt << 7) + g * 8 + pe;
            Pw[base]          = f2tf32(s[nt][0]);
            Pw[base + 2]      = f2tf32(s[nt][1]);
            Pw[base + 64]     = f2tf32(s[nt][2]);
            Pw[base + 64 + 2] = f2tf32(s[nt][3]);
        }
        __syncwarp();

        #pragma unroll
        for (int ks = 0; ks < 16; ks++) {
            uint2 a0 = *(const uint2*)&Pw[(ks << 7) + g * 8 + tig * 2];
            uint2 a1 = *(const uint2*)&Pw[(ks << 7) + (g + 8) * 8 + tig * 2];
            uint32_t af[4] = {a0.x, a1.x, a0.y, a1.y};
            #pragma unroll
            for (int nt = 0; nt < 8; nt++) {
                uint2 bb = *(const uint2*)&Vs[ks * 640 + (nt * 8 + g) * 10 + tig * 2];
                mma_tf32(o[nt], af, bb.x, bb.y);
            }
        }
    }

    float invA = 1.f / lA, invB = 1.f / lB;
    int tA = t0 + wr0 + g, tB = tA + 8;
    #pragma unroll
    for (int nt = 0; nt < 8; nt++) {
        int hd = nt * 8 + tig * 2;
        float2 vA = make_float2(o[nt][0] * invA, o[nt][1] * invA);
        float2 vB = make_float2(o[nt][2] * invB, o[nt][3] * invB);
        *(float2*)(ctx + ((size_t)tA * BB + b) * DD + h * HDD + hd) = vA;
        *(float2*)(ctx + ((size_t)tB * BB + b) * DD + h * HDD + hd) = vB;
        if (attn) {
            *(float2*)(attn + (((size_t)h * BB + b) * TT + tA) * HDD + hd) = vA;
            *(float2*)(attn + (((size_t)h * BB + b) * TT + tB) * HDD + hd) = vB;
        }
    }
}

// ---------------- fused residual add + layernorm
__global__ __launch_bounds__(256) void add_ln_kernel(
    const float* __restrict__ a, const float* __restrict__ r,
    const float* __restrict__ g, const float* __restrict__ be,
    float* __restrict__ o)
{
    size_t row = blockIdx.x;
    int tid = threadIdx.x;
    float4 va = *(const float4*)(a + row * DD + tid * 4);
    float4 vr = *(const float4*)(r + row * DD + tid * 4);
    float x0 = va.x + vr.x, x1 = va.y + vr.y, x2 = va.z + vr.z, x3 = va.w + vr.w;
    float s  = block_sum(x0 + x1 + x2 + x3);
    float mu = s * (1.f / DD);
    float d0 = x0 - mu, d1 = x1 - mu, d2 = x2 - mu, d3 = x3 - mu;
    float sq = block_sum(d0 * d0 + d1 * d1 + d2 * d2 + d3 * d3);
    float inv = rsqrtf(sq * (1.f / DD) + 1e-5f);
    float4 vg = *(const float4*)(g + tid * 4);
    float4 vb = *(const float4*)(be + tid * 4);
    float4 out;
    out.x = d0 * inv * vg.x + vb.x;
    out.y = d1 * inv * vg.y + vb.y;
    out.z = d2 * inv * vg.z + vb.z;
    out.w = d3 * inv * vg.w + vb.w;
    *(float4*)(o + row * DD + tid * 4) = out;
}

// ---------------- host launch ----------------
extern "C" void kernel_launch(void* const* d_in, const int* in_sizes, int n_in,
                              void* d_out, int out_size)
{
    const float* state = (const float*)d_in[0];
    const float* enc   = (const float*)d_in[1];
    const float* amask = (const float*)d_in[2];
    const int* spad = (const int*)d_in[3];
    const int* epad = (const int*)d_in[4];
    const float *saWq = (const float*)d_in[5],  *sabq = (const float*)d_in[6];
    const float *saWk = (const float*)d_in[7],  *sabk = (const float*)d_in[8];
    const float *saWv = (const float*)d_in[9],  *sabv = (const float*)d_in[10];
    const float *saWo = (const float*)d_in[11], *sabo = (const float*)d_in[12];
    const float *eaWq = (const float*)d_in[13], *eabq = (const float*)d_in[14];
    const float *eaWk = (const float*)d_in[15], *eabk = (const float*)d_in[16];
    const float *eaWv = (const float*)d_in[17], *eabv = (const float*)d_in[18];
    const float *eaWo = (const float*)d_in[19], *eabo = (const float*)d_in[20];
    const float *ln1g = (const float*)d_in[21], *ln1b = (const float*)d_in[22];
    const float *ln2g = (const float*)d_in[23], *ln2b = (const float*)d_in[24];
    const float *ln3g = (const float*)d_in[25], *ln3b = (const float*)d_in[26];
    const float *fc1W = (const float*)d_in[27], *fc1b = (const float*)d_in[28];
    const float *fc2W = (const float*)d_in[29], *fc2b = (const float*)d_in[30];

    float *q, *k, *v, *ctx, *tmp, *x1, *x2, *ffn, *rss, *rse;
    cudaGetSymbolAddress((void**)&q,   g_q);
    cudaGetSymbolAddress((void**)&k,   g_k);
    cudaGetSymbolAddress((void**)&v,   g_v);
    cudaGetSymbolAddress((void**)&ctx, g_ctx);
    cudaGetSymbolAddress((void**)&tmp, g_tmp);
    cudaGetSymbolAddress((void**)&x1,  g_x1);
    cudaGetSymbolAddress((void**)&x2,  g_x2);
    cudaGetSymbolAddress((void**)&ffn, g_ffn);
    cudaGetSymbolAddress((void**)&rss, g_rs_self);
    cudaGetSymbolAddress((void**)&rse, g_rs_enc);

    const int GSM = 32768;
    const int FSM = FL_SMEM_WORDS * 4;
    cudaFuncSetAttribute(gemm_tf32_kernel,  cudaFuncAttributeMaxDynamicSharedMemorySize, GSM);
    cudaFuncSetAttribute(flash_tf32_kernel, cudaFuncAttributeMaxDynamicSharedMemorySize, FSM);

    float* outx = (float*)d_out;
    float* outa = outx + (size_t)MM * DD;

    expand_mask_kernel<<<(MM + 255) / 256, 256>>>(spad, rss, TT);
    expand_mask_kernel<<<(MM + 255) / 256, 256>>>(epad, rse, SSZ);

    dim3 gP(DD / 128, MM / 128);
    dim3 gF1(FFND / 128, MM / 128);
    dim3 gFl(TT / 128, BB * HH);

    // ---- self-attention ----
    gemm_tf32_kernel<<<gP, 256, GSM>>>(state, saWq, sabq, nullptr, q, MM, DD, DD, 0);
    gemm_tf32_kernel<<<gP, 256, GSM>>>(state, saWk, sabk, rss,     k, MM, DD, DD, 0);
    gemm_tf32_kernel<<<gP, 256, GSM>>>(state, saWv, sabv, nullptr, v, MM, DD, DD, 0);
    flash_tf32_kernel<<<gFl, 256, FSM>>>(q, k, v, amask, ctx, nullptr, 1);
    gemm_tf32_kernel<<<gP, 256, GSM>>>(ctx, saWo, sabo, nullptr, tmp, MM, DD, DD, 0);
    add_ln_kernel<<<MM, 256>>>(tmp, state, ln1g, ln1b, x1);

    // ---- encoder-decoder attention ----
    gemm_tf32_kernel<<<gP, 256, GSM>>>(x1,  eaWq, eabq, nullptr, q, MM, DD, DD, 0);
    gemm_tf32_kernel<<<gP, 256, GSM>>>(enc, eaWk, eabk, rse,     k, MM, DD, DD, 0);
    gemm_tf32_kernel<<<gP, 256, GSM>>>(enc, eaWv, eabv, nullptr, v, MM, DD, DD, 0);
    flash_tf32_kernel<<<gFl, 256, FSM>>>(q, k, v, nullptr, ctx, outa, 0);
    gemm_tf32_kernel<<<gP, 256, GSM>>>(ctx, eaWo, eabo, nullptr, tmp, MM, DD, DD, 0);
    add_ln_kernel<<<MM, 256>>>(tmp, x1, ln2g, ln2b, x2);

    // ---- FFN ----
    gemm_tf32_kernel<<<gF1, 256, GSM>>>(x2, fc1W, fc1b, nullptr, ffn, MM, FFND, DD, 1);
    gemm_tf32_kernel<<<gP, 256, GSM>>>(ffn, fc2W, fc2b, nullptr, tmp, MM, DD, FFND, 0);
    add_ln_kernel<<<MM, 256>>>(tmp, x2, ln3g, ln3b, outx);
}

// round 7
// speedup vs baseline: 1.3466x; 1.1276x over previous
#include <cuda_runtime.h>
#include <math.h>
#include <stdint.h>

#define TT   1024
#define SSZ  1024
#define BB   4
#define DD   1024
#define HH   16
#define HDD  64
#define FFND 4096
#define MM   (TT*BB)

// ---------------- scratch (device globals; no allocs allowed) ----------------
__device__ float g_q[MM*DD];
__device__ float g_k[MM*DD];
__device__ float g_v[MM*DD];
__device__ float g_ctx[MM*DD];
__device__ float g_tmp[MM*DD];
__device__ float g_x1[MM*DD];
__device__ float g_x2[MM*DD];
__device__ float g_ffn[(size_t)MM*FFND];
__device__ float g_rs_self[MM];
__device__ float g_rs_enc[MM];
__device__ uint32_t g_wtf[16*1024*1024];   // tf32 copies of all weights (64MB)

#define WOFF_SAQ  (0*1048576)
#define WOFF_SAK  (1*1048576)
#define WOFF_SAV  (2*1048576)
#define WOFF_SAO  (3*1048576)
#define WOFF_EAQ  (4*1048576)
#define WOFF_EAK  (5*1048576)
#define WOFF_EAV  (6*1048576)
#define WOFF_EAO  (7*1048576)
#define WOFF_FC1  (8*1048576)
#define WOFF_FC2  (12*1048576)

// ---------------- helpers ----------------
__device__ __forceinline__ float block_sum(float v) {
    __shared__ float sh[8];
    __shared__ float res;
    int lane = threadIdx.x & 31, w = threadIdx.x >> 5;
    #pragma unroll
    for (int o = 16; o > 0; o >>= 1) v += __shfl_xor_sync(0xffffffffu, v, o);
    __syncthreads();
    if (lane == 0) sh[w] = v;
    __syncthreads();
    if (threadIdx.x == 0) {
        float t = 0.f;
        #pragma unroll
        for (int i = 0; i < 8; i++) t += sh[i];
        res = t;
    }
    __syncthreads();
    return res;
}

__device__ __forceinline__ uint32_t f2tf32(float x) {
    uint32_t u;
    asm("cvt.rna.tf32.f32 %0, %1;" : "=r"(u) : "f"(x));
    return u;
}

__device__ __forceinline__ void mma_tf32(float* d, const uint32_t* a, uint32_t b0, uint32_t b1) {
    asm volatile(
        "mma.sync.aligned.m16n8k8.row.col.f32.tf32.tf32.f32 "
        "{%0,%1,%2,%3}, {%4,%5,%6,%7}, {%8,%9}, {%0,%1,%2,%3};"
        : "+f"(d[0]), "+f"(d[1]), "+f"(d[2]), "+f"(d[3])
        : "r"(a[0]), "r"(a[1]), "r"(a[2]), "r"(a[3]), "r"(b0), "r"(b1));
}

__global__ void expand_mask_kernel(const int* __restrict__ mask,
                                   float* __restrict__ rowscale, int L) {
    int r = blockIdx.x * blockDim.x + threadIdx.x;
    if (r < L * BB) {
        int pos = r / BB, b = r % BB;
        rowscale[r] = mask[b * L + pos] ? 0.f : 1.f;
    }
}

// ---------------- weight pre-conversion fp32 -> tf32 words ----------------
__global__ __launch_bounds__(256) void cvt_tf32_kernel(
    const float* __restrict__ src, uint32_t* __restrict__ dst, int n)
{
    int i = (blockIdx.x * blockDim.x + threadIdx.x) * 4;
    if (i < n) {
        float4 v = *(const float4*)(src + i);
        uint4 o;
        o.x = f2tf32(v.x); o.y = f2tf32(v.y);
        o.z = f2tf32(v.z); o.w = f2tf32(v.w);
        *(uint4*)(dst + i) = o;
    }
}

// =====================================================================
// TF32 GEMM (round-3 structure): C[M,N] = A[M,K] @ W[N,K]^T + bias.
// W is pre-converted tf32 words. 128x128x32 tile, 256 thr, SKEW smem,
// single buffer, register prefetch, 2 syncs per k-tile.
// =====================================================================
#define SKEW 36
__global__ __launch_bounds__(256) void gemm_tf32_kernel(
    const float* __restrict__ A, const uint32_t* __restrict__ W,
    const float* __restrict__ bias, const float* __restrict__ rowscale,
    float* __restrict__ C, int M, int N, int K, int relu)
{
    __shared__ uint32_t As[128][SKEW];
    __shared__ uint32_t Ws[128][SKEW];
    const int tid = threadIdx.x;
    const int lane = tid & 31, warp = tid >> 5;
    const int wm = warp & 3, wn = warp >> 2;
    const int g = lane >> 2, tig = lane & 3;
    const int bx = blockIdx.x, by = blockIdx.y;

    float d[2][8][4];
    #pragma unroll
    for (int mt = 0; mt < 2; mt++)
        #pragma unroll
        for (int nt = 0; nt < 8; nt++)
            #pragma unroll
            for (int i = 0; i < 4; i++) d[mt][nt][i] = 0.f;

    float4 aReg[4];
    uint4  wReg[4];
    float ascale[4];
    int arow[4], wrow[4], rv[4], cv[4];
    #pragma unroll
    for (int i = 0; i < 4; i++) {
        int f = tid + (i << 8);
        rv[i] = f >> 3;
        cv[i] = (f & 7) << 2;
        arow[i] = by * 128 + rv[i];
        wrow[i] = bx * 128 + rv[i];
        ascale[i] = rowscale ? rowscale[arow[i]] : 1.f;
    }

    auto load_regs = [&](int k0) {
        #pragma unroll
        for (int i = 0; i < 4; i++) {
            aReg[i] = *(const float4*)(A + (size_t)arow[i] * K + k0 + cv[i]);
            wReg[i] = *(const uint4*)(W + (size_t)wrow[i] * K + k0 + cv[i]);
        }
    };
    auto store_smem = [&]() {
        #pragma unroll
        for (int i = 0; i < 4; i++) {
            int r = rv[i], c4 = cv[i];
            float s = ascale[i];
            As[r][c4 + 0] = f2tf32(aReg[i].x * s);
            As[r][c4 + 1] = f2tf32(aReg[i].y * s);
            As[r][c4 + 2] = f2tf32(aReg[i].z * s);
            As[r][c4 + 3] = f2tf32(aReg[i].w * s);
            Ws[r][c4 + 0] = wReg[i].x;
            Ws[r][c4 + 1] = wReg[i].y;
            Ws[r][c4 + 2] = wReg[i].z;
            Ws[r][c4 + 3] = wReg[i].w;
        }
    };

    load_regs(0);
    store_smem();
    __syncthreads();

    for (int k0 = 0; k0 < K; k0 += 32) {
        bool has_next = (k0 + 32) < K;
        if (has_next) load_regs(k0 + 32);

        #pragma unroll
        for (int ks = 0; ks < 4; ks++) {
            int kb = ks * 8;
            uint32_t af[2][4];
            #pragma unroll
            for (int mt = 0; mt < 2; mt++) {
                int ar = wm * 32 + mt * 16 + g;
                af[mt][0] = As[ar][kb + tig];
                af[mt][1] = As[ar + 8][kb + tig];
                af[mt][2] = As[ar][kb + tig + 4];
                af[mt][3] = As[ar + 8][kb + tig + 4];
            }
            #pragma unroll
            for (int nt = 0; nt < 8; nt++) {
                int bc = wn * 64 + nt * 8 + g;
                uint32_t b0 = Ws[bc][kb + tig];
                uint32_t b1 = Ws[bc][kb + tig + 4];
                mma_tf32(d[0][nt], af[0], b0, b1);
                mma_tf32(d[1][nt], af[1], b0, b1);
            }
        }

        if (has_next) {
            __syncthreads();
            store_smem();
            __syncthreads();
        }
    }

    #pragma unroll
    for (int mt = 0; mt < 2; mt++) {
        int row0 = by * 128 + wm * 32 + mt * 16 + g;
        #pragma unroll
        for (int nt = 0; nt < 8; nt++) {
            int col = bx * 128 + wn * 64 + nt * 8 + tig * 2;
            float b0 = bias[col], b1 = bias[col + 1];
            float v00 = d[mt][nt][0] + b0, v01 = d[mt][nt][1] + b1;
            float v10 = d[mt][nt][2] + b0, v11 = d[mt][nt][3] + b1;
            if (relu) {
                v00 = fmaxf(v00, 0.f); v01 = fmaxf(v01, 0.f);
                v10 = fmaxf(v10, 0.f); v11 = fmaxf(v11, 0.f);
            }
            *(float2*)(C + (size_t)row0 * N + col)       = make_float2(v00, v01);
            *(float2*)(C + (size_t)(row0 + 8) * N + col) = make_float2(v10, v11);
        }
    }
}

// =====================================================================
// Fused flash attention (tf32) — unchanged (measured good).
// =====================================================================
#define FQ 0
#define FK 8192
#define FV 16384
#define FP 26624
#define FL_SMEM_WORDS 43008

__global__ __launch_bounds__(256) void flash_tf32_kernel(
    const float* __restrict__ Q, const float* __restrict__ Kk,
    const float* __restrict__ V, const float* __restrict__ mask,
    float* __restrict__ ctx, float* __restrict__ attn, int causal)
{
    extern __shared__ uint32_t sm[];
    uint32_t* Qs = sm + FQ;
    uint32_t* Ks = sm + FK;
    uint32_t* Vs = sm + FV;
    const int tid = threadIdx.x;
    const int lane = tid & 31, warp = tid >> 5;
    const int g = lane >> 2, tig = lane & 3;
    const int bh = blockIdx.y;
    const int b = bh / HH, h = bh % HH;
    const int t0 = blockIdx.x * 128;
    const int wr0 = warp * 16;
    uint32_t* Pw = sm + FP + warp * 2048;

    #pragma unroll
    for (int i = 0; i < 8; i++) {
        int f = tid + (i << 8);
        int r = f >> 4;
        int c4 = (f & 15) << 2;
        int bse = ((c4 >> 3) << 10) + (r << 3) + ((c4 >> 2) & 1);
        float4 q4 = *(const float4*)(Q + ((size_t)(t0 + r) * BB + b) * DD + h * HDD + c4);
        Qs[bse + 0] = f2tf32(q4.x); Qs[bse + 2] = f2tf32(q4.y);
        Qs[bse + 4] = f2tf32(q4.z); Qs[bse + 6] = f2tf32(q4.w);
    }

    float mA = -1e30f, mB = -1e30f, lA = 0.f, lB = 0.f;
    float o[8][4];
    #pragma unroll
    for (int nt = 0; nt < 8; nt++)
        #pragma unroll
        for (int i = 0; i < 4; i++) o[nt][i] = 0.f;

    const int pe = ((tig * 2) & 3) * 2 + (tig >> 1);
    const int n_stiles = causal ? (blockIdx.x + 1) : (SSZ / 128);

    for (int is = 0; is < n_stiles; is++) {
        int s0 = is * 128;
        __syncthreads();

        #pragma unroll
        for (int i = 0; i < 8; i++) {
            int f = tid + (i << 8);
            int r = f >> 4;
            int c4 = (f & 15) << 2;
            int bse = ((c4 >> 3) << 10) + (r << 3) + ((c4 >> 2) & 1);
            float4 k4 = *(const float4*)(Kk + ((size_t)(s0 + r) * BB + b) * DD + h * HDD + c4);
            Ks[bse + 0] = f2tf32(k4.x); Ks[bse + 2] = f2tf32(k4.y);
            Ks[bse + 4] = f2tf32(k4.z); Ks[bse + 6] = f2tf32(k4.w);
            float4 v4 = *(const float4*)(V + ((size_t)(s0 + r) * BB + b) * DD + h * HDD + c4);
            int vb = ((r >> 3) * 640) + ((r & 3) << 1) + ((r >> 2) & 1);
            Vs[vb + (c4 + 0) * 10] = f2tf32(v4.x);
            Vs[vb + (c4 + 1) * 10] = f2tf32(v4.y);
            Vs[vb + (c4 + 2) * 10] = f2tf32(v4.z);
            Vs[vb + (c4 + 3) * 10] = f2tf32(v4.w);
        }
        __syncthreads();

        float s[16][4];
        #pragma unroll
        for (int nt = 0; nt < 16; nt++)
            #pragma unroll
            for (int i = 0; i < 4; i++) s[nt][i] = 0.f;

        #pragma unroll
        for (int ks = 0; ks < 8; ks++) {
            int ab = ks << 10;
            uint2 a0 = *(const uint2*)&Qs[ab + (wr0 + g) * 8 + tig * 2];
            uint2 a1 = *(const uint2*)&Qs[ab + (wr0 + 8 + g) * 8 + tig * 2];
            uint32_t af[4] = {a0.x, a1.x, a0.y, a1.y};
            #pragma unroll
            for (int nt = 0; nt < 16; nt++) {
                uint2 bb = *(const uint2*)&Ks[ab + (nt * 8 + g) * 8 + tig * 2];
                mma_tf32(s[nt], af, bb.x, bb.y);
            }
        }

        const float scale = 0.125f;
        if (causal && is == blockIdx.x) {
            int tAr = t0 + wr0 + g, tBr = tAr + 8;
            #pragma unroll
            for (int nt = 0; nt < 16; nt++) {
                int c = s0 + nt * 8 + tig * 2;
                s[nt][0] = s[nt][0] * scale + mask[(size_t)tAr * TT + c];
                s[nt][1] = s[nt][1] * scale + mask[(size_t)tAr * TT + c + 1];
                s[nt][2] = s[nt][2] * scale + mask[(size_t)tBr * TT + c];
                s[nt][3] = s[nt][3] * scale + mask[(size_t)tBr * TT + c + 1];
            }
        } else {
            #pragma unroll
            for (int nt = 0; nt < 16; nt++)
                #pragma unroll
                for (int i = 0; i < 4; i++) s[nt][i] *= scale;
        }

        float mtA = -1e30f, mtB = -1e30f;
        #pragma unroll
        for (int nt = 0; nt < 16; nt++) {
            mtA = fmaxf(mtA, fmaxf(s[nt][0], s[nt][1]));
            mtB = fmaxf(mtB, fmaxf(s[nt][2], s[nt][3]));
        }
        mtA = fmaxf(mtA, __shfl_xor_sync(0xffffffffu, mtA, 1));
        mtA = fmaxf(mtA, __shfl_xor_sync(0xffffffffu, mtA, 2));
        mtB = fmaxf(mtB, __shfl_xor_sync(0xffffffffu, mtB, 1));
        mtB = fmaxf(mtB, __shfl_xor_sync(0xffffffffu, mtB, 2));

        float mnA = fmaxf(mA, mtA), mnB = fmaxf(mB, mtB);
        float alA = __expf(mA - mnA), alB = __expf(mB - mnB);
        float rsA = 0.f, rsB = 0.f;
        #pragma unroll
        for (int nt = 0; nt < 16; nt++) {
            s[nt][0] = __expf(s[nt][0] - mnA);
            s[nt][1] = __expf(s[nt][1] - mnA);
            s[nt][2] = __expf(s[nt][2] - mnB);
            s[nt][3] = __expf(s[nt][3] - mnB);
            rsA += s[nt][0] + s[nt][1];
            rsB += s[nt][2] + s[nt][3];
        }
        rsA += __shfl_xor_sync(0xffffffffu, rsA, 1);
        rsA += __shfl_xor_sync(0xffffffffu, rsA, 2);
        rsB += __shfl_xor_sync(0xffffffffu, rsB, 1);
        rsB += __shfl_xor_sync(0xffffffffu, rsB, 2);
        lA = lA * alA + rsA; mA = mnA;
        lB = lB * alB + rsB; mB = mnB;

        #pragma unroll
        for (int nt = 0; nt < 8; nt++) {
            o[nt][0] *= alA; o[nt][1] *= alA;
            o[nt][2] *= alB; o[nt][3] *= alB;
        }

        __syncwarp();
        #pragma unroll
        for (int nt = 0; nt < 16; nt++) {
            int base = (nt << 7) + g * 8 + pe;
            Pw[base]          = f2tf32(s[nt][0]);
            Pw[base + 2]      = f2tf32(s[nt][1]);
            Pw[base + 64]     = f2tf32(s[nt][2]);
            Pw[base + 64 + 2] = f2tf32(s[nt][3]);
        }
        __syncwarp();

        #pragma unroll
        for (int ks = 0; ks < 16; ks++) {
            uint2 a0 = *(const uint2*)&Pw[(ks << 7) + g * 8 + tig * 2];
            uint2 a1 = *(const uint2*)&Pw[(ks << 7) + (g + 8) * 8 + tig * 2];
            uint32_t af[4] = {a0.x, a1.x, a0.y, a1.y};
            #pragma unroll
            for (int nt = 0; nt < 8; nt++) {
                uint2 bb = *(const uint2*)&Vs[ks * 640 + (nt * 8 + g) * 10 + tig * 2];
                mma_tf32(o[nt], af, bb.x, bb.y);
            }
        }
    }

    float invA = 1.f / lA, invB = 1.f / lB;
    int tA = t0 + wr0 + g, tB = tA + 8;
    #pragma unroll
    for (int nt = 0; nt < 8; nt++) {
        int hd = nt * 8 + tig * 2;
        float2 vA = make_float2(o[nt][0] * invA, o[nt][1] * invA);
        float2 vB = make_float2(o[nt][2] * invB, o[nt][3] * invB);
        *(float2*)(ctx + ((size_t)tA * BB + b) * DD + h * HDD + hd) = vA;
        *(float2*)(ctx + ((size_t)tB * BB + b) * DD + h * HDD + hd) = vB;
        if (attn) {
            *(float2*)(attn + (((size_t)h * BB + b) * TT + tA) * HDD + hd) = vA;
            *(float2*)(attn + (((size_t)h * BB + b) * TT + tB) * HDD + hd) = vB;
        }
    }
}

// ---------------- fused residual add + layernorm
__global__ __launch_bounds__(256) void add_ln_kernel(
    const float* __restrict__ a, const float* __restrict__ r,
    const float* __restrict__ g, const float* __restrict__ be,
    float* __restrict__ o)
{
    size_t row = blockIdx.x;
    int tid = threadIdx.x;
    float4 va = *(const float4*)(a + row * DD + tid * 4);
    float4 vr = *(const float4*)(r + row * DD + tid * 4);
    float x0 = va.x + vr.x, x1 = va.y + vr.y, x2 = va.z + vr.z, x3 = va.w + vr.w;
    float s  = block_sum(x0 + x1 + x2 + x3);
    float mu = s * (1.f / DD);
    float d0 = x0 - mu, d1 = x1 - mu, d2 = x2 - mu, d3 = x3 - mu;
    float sq = block_sum(d0 * d0 + d1 * d1 + d2 * d2 + d3 * d3);
    float inv = rsqrtf(sq * (1.f / DD) + 1e-5f);
    float4 vg = *(const float4*)(g + tid * 4);
    float4 vb = *(const float4*)(be + tid * 4);
    float4 out;
    out.x = d0 * inv * vg.x + vb.x;
    out.y = d1 * inv * vg.y + vb.y;
    out.z = d2 * inv * vg.z + vb.z;
    out.w = d3 * inv * vg.w + vb.w;
    *(float4*)(o + row * DD + tid * 4) = out;
}

// ---------------- host launch ----------------
extern "C" void kernel_launch(void* const* d_in, const int* in_sizes, int n_in,
                              void* d_out, int out_size)
{
    const float* state = (const float*)d_in[0];
    const float* enc   = (const float*)d_in[1];
    const float* amask = (const float*)d_in[2];
    const int* spad = (const int*)d_in[3];
    const int* epad = (const int*)d_in[4];
    const float *saWq = (const float*)d_in[5],  *sabq = (const float*)d_in[6];
    const float *saWk = (const float*)d_in[7],  *sabk = (const float*)d_in[8];
    const float *saWv = (const float*)d_in[9],  *sabv = (const float*)d_in[10];
    const float *saWo = (const float*)d_in[11], *sabo = (const float*)d_in[12];
    const float *eaWq = (const float*)d_in[13], *eabq = (const float*)d_in[14];
    const float *eaWk = (const float*)d_in[15], *eabk = (const float*)d_in[16];
    const float *eaWv = (const float*)d_in[17], *eabv = (const float*)d_in[18];
    const float *eaWo = (const float*)d_in[19], *eabo = (const float*)d_in[20];
    const float *ln1g = (const float*)d_in[21], *ln1b = (const float*)d_in[22];
    const float *ln2g = (const float*)d_in[23], *ln2b = (const float*)d_in[24];
    const float *ln3g = (const float*)d_in[25], *ln3b = (const float*)d_in[26];
    const float *fc1W = (const float*)d_in[27], *fc1b = (const float*)d_in[28];
    const float *fc2W = (const float*)d_in[29], *fc2b = (const float*)d_in[30];

    float *q, *k, *v, *ctx, *tmp, *x1, *x2, *ffn, *rss, *rse;
    uint32_t* wtf;
    cudaGetSymbolAddress((void**)&q,   g_q);
    cudaGetSymbolAddress((void**)&k,   g_k);
    cudaGetSymbolAddress((void**)&v,   g_v);
    cudaGetSymbolAddress((void**)&ctx, g_ctx);
    cudaGetSymbolAddress((void**)&tmp, g_tmp);
    cudaGetSymbolAddress((void**)&x1,  g_x1);
    cudaGetSymbolAddress((void**)&x2,  g_x2);
    cudaGetSymbolAddress((void**)&ffn, g_ffn);
    cudaGetSymbolAddress((void**)&rss, g_rs_self);
    cudaGetSymbolAddress((void**)&rse, g_rs_enc);
    cudaGetSymbolAddress((void**)&wtf, g_wtf);

    const int FSM = FL_SMEM_WORDS * 4;
    cudaFuncSetAttribute(flash_tf32_kernel, cudaFuncAttributeMaxDynamicSharedMemorySize, FSM);

    float* outx = (float*)d_out;
    float* outa = outx + (size_t)MM * DD;

    // ---- pre-convert weights to tf32 ----
    const int NW = DD * DD;         // 1M
    const int NF = FFND * DD;       // 4M
    dim3 cvB(256);
    cvt_tf32_kernel<<<NW / 1024, cvB>>>(saWq, wtf + WOFF_SAQ, NW);
    cvt_tf32_kernel<<<NW / 1024, cvB>>>(saWk, wtf + WOFF_SAK, NW);
    cvt_tf32_kernel<<<NW / 1024, cvB>>>(saWv, wtf + WOFF_SAV, NW);
    cvt_tf32_kernel<<<NW / 1024, cvB>>>(saWo, wtf + WOFF_SAO, NW);
    cvt_tf32_kernel<<<NW / 1024, cvB>>>(eaWq, wtf + WOFF_EAQ, NW);
    cvt_tf32_kernel<<<NW / 1024, cvB>>>(eaWk, wtf + WOFF_EAK, NW);
    cvt_tf32_kernel<<<NW / 1024, cvB>>>(eaWv, wtf + WOFF_EAV, NW);
    cvt_tf32_kernel<<<NW / 1024, cvB>>>(eaWo, wtf + WOFF_EAO, NW);
    cvt_tf32_kernel<<<NF / 1024, cvB>>>(fc1W, wtf + WOFF_FC1, NF);
    cvt_tf32_kernel<<<NF / 1024, cvB>>>(fc2W, wtf + WOFF_FC2, NF);

    expand_mask_kernel<<<(MM + 255) / 256, 256>>>(spad, rss, TT);
    expand_mask_kernel<<<(MM + 255) / 256, 256>>>(epad, rse, SSZ);

    dim3 gP(DD / 128, MM / 128);
    dim3 gF1(FFND / 128, MM / 128);
    dim3 gFl(TT / 128, BB * HH);

    // ---- self-attention ----
    gemm_tf32_kernel<<<gP, 256>>>(state, wtf + WOFF_SAQ, sabq, nullptr, q, MM, DD, DD, 0);
    gemm_tf32_kernel<<<gP, 256>>>(state, wtf + WOFF_SAK, sabk, rss,     k, MM, DD, DD, 0);
    gemm_tf32_kernel<<<gP, 256>>>(state, wtf + WOFF_SAV, sabv, nullptr, v, MM, DD, DD, 0);
    flash_tf32_kernel<<<gFl, 256, FSM>>>(q, k, v, amask, ctx, nullptr, 1);
    gemm_tf32_kernel<<<gP, 256>>>(ctx, wtf + WOFF_SAO, sabo, nullptr, tmp, MM, DD, DD, 0);
    add_ln_kernel<<<MM, 256>>>(tmp, state, ln1g, ln1b, x1);

    // ---- encoder-decoder attention ----
    gemm_tf32_kernel<<<gP, 256>>>(x1,  wtf + WOFF_EAQ, eabq, nullptr, q, MM, DD, DD, 0);
    gemm_tf32_kernel<<<gP, 256>>>(enc, wtf + WOFF_EAK, eabk, rse,     k, MM, DD, DD, 0);
    gemm_tf32_kernel<<<gP, 256>>>(enc, wtf + WOFF_EAV, eabv, nullptr, v, MM, DD, DD, 0);
    flash_tf32_kernel<<<gFl, 256, FSM>>>(q, k, v, nullptr, ctx, outa, 0);
    gemm_tf32_kernel<<<gP, 256>>>(ctx, wtf + WOFF_EAO, eabo, nullptr, tmp, MM, DD, DD, 0);
    add_ln_kernel<<<MM, 256>>>(tmp, x1, ln2g, ln2b, x2);

    // ---- FFN ----
    gemm_tf32_kernel<<<gF1, 256>>>(x2, wtf + WOFF_FC1, fc1b, nullptr, ffn, MM, FFND, DD, 1);
    gemm_tf32_kernel<<<gP, 256>>>(ffn, wtf + WOFF_FC2, fc2b, nullptr, tmp, MM, DD, FFND, 0);
    add_ln_kernel<<<MM, 256>>>(tmp, x2, ln3g, ln3b, outx);
}

// round 8
// speedup vs baseline: 1.5569x; 1.1561x over previous
#include <cuda_runtime.h>
#include <math.h>
#include <stdint.h>

#define TT   1024
#define SSZ  1024
#define BB   4
#define DD   1024
#define HH   16
#define HDD  64
#define FFND 4096
#define MM   (TT*BB)

// ---------------- scratch (device globals; no allocs allowed) ----------------
__device__ uint32_t g_state_t[MM*DD];
__device__ uint32_t g_enc_t[MM*DD];
__device__ uint32_t g_qt[MM*DD];
__device__ uint32_t g_kt[MM*DD];
__device__ uint32_t g_vt[MM*DD];
__device__ uint32_t g_ctx_t[MM*DD];
__device__ float    g_tmp[MM*DD];
__device__ float    g_x1[MM*DD];
__device__ uint32_t g_x1t[MM*DD];
__device__ float    g_x2[MM*DD];
__device__ uint32_t g_x2t[MM*DD];
__device__ uint32_t g_ffn_t[(size_t)MM*FFND];
__device__ float    g_rs_self[MM];
__device__ float    g_rs_enc[MM];
__device__ uint32_t g_wtf[16*1024*1024];   // tf32 weights (64MB)

#define WOFF_SAQ  (0*1048576)
#define WOFF_SAK  (1*1048576)
#define WOFF_SAV  (2*1048576)
#define WOFF_SAO  (3*1048576)
#define WOFF_EAQ  (4*1048576)
#define WOFF_EAK  (5*1048576)
#define WOFF_EAV  (6*1048576)
#define WOFF_EAO  (7*1048576)
#define WOFF_FC1  (8*1048576)
#define WOFF_FC2  (12*1048576)

// ---------------- helpers ----------------
__device__ __forceinline__ float block_sum(float v) {
    __shared__ float sh[8];
    __shared__ float res;
    int lane = threadIdx.x & 31, w = threadIdx.x >> 5;
    #pragma unroll
    for (int o = 16; o > 0; o >>= 1) v += __shfl_xor_sync(0xffffffffu, v, o);
    __syncthreads();
    if (lane == 0) sh[w] = v;
    __syncthreads();
    if (threadIdx.x == 0) {
        float t = 0.f;
        #pragma unroll
        for (int i = 0; i < 8; i++) t += sh[i];
        res = t;
    }
    __syncthreads();
    return res;
}

__device__ __forceinline__ uint32_t f2tf32(float x) {
    uint32_t u;
    asm("cvt.rna.tf32.f32 %0, %1;" : "=r"(u) : "f"(x));
    return u;
}

__device__ __forceinline__ void mma_tf32(float* d, const uint32_t* a, uint32_t b0, uint32_t b1) {
    asm volatile(
        "mma.sync.aligned.m16n8k8.row.col.f32.tf32.tf32.f32 "
        "{%0,%1,%2,%3}, {%4,%5,%6,%7}, {%8,%9}, {%0,%1,%2,%3};"
        : "+f"(d[0]), "+f"(d[1]), "+f"(d[2]), "+f"(d[3])
        : "r"(a[0]), "r"(a[1]), "r"(a[2]), "r"(a[3]), "r"(b0), "r"(b1));
}

__global__ void expand_mask_kernel(const int* __restrict__ mask,
                                   float* __restrict__ rowscale, int L) {
    int r = blockIdx.x * blockDim.x + threadIdx.x;
    if (r < L * BB) {
        int pos = r / BB, b = r % BB;
        rowscale[r] = mask[b * L + pos] ? 0.f : 1.f;
    }
}

// ---------------- fp32 -> tf32 words ----------------
__global__ __launch_bounds__(256) void cvt_tf32_kernel(
    const float* __restrict__ src, uint32_t* __restrict__ dst, int n)
{
    int i = (blockIdx.x * blockDim.x + threadIdx.x) * 4;
    if (i < n) {
        float4 v = *(const float4*)(src + i);
        uint4 o;
        o.x = f2tf32(v.x); o.y = f2tf32(v.y);
        o.z = f2tf32(v.z); o.w = f2tf32(v.w);
        *(uint4*)(dst + i) = o;
    }
}

// =====================================================================
// TF32 GEMM: out = A[M,K] @ W[N,K]^T (rowscale in epilogue) + bias.
// A and W are pre-converted tf32 words. 128x128x32 tile, 256 thr,
// 2 CTAs/SM, cp.async double-buffered SKEW-36 smem.
// Dynamic smem = 2 stages * 2 * 128*36 words * 4B = 73728 B.
// =====================================================================
#define SKEW 36
#define ASTG_W (128*SKEW)        // 4608 words per matrix region
#define STG_W  (2*ASTG_W)        // 9216 words per stage

__global__ __launch_bounds__(256, 2) void gemm_tf32_kernel(
    const uint32_t* __restrict__ A, const uint32_t* __restrict__ W,
    const float* __restrict__ bias, const float* __restrict__ rowscale,
    float* __restrict__ C, uint32_t* __restrict__ Ct,
    int M, int N, int K, int relu)
{
    extern __shared__ uint32_t sm[];
    const int tid = threadIdx.x;
    const int lane = tid & 31, warp = tid >> 5;
    const int wm = warp & 3, wn = warp >> 2;
    const int g = lane >> 2, tig = lane & 3;
    const int bx = blockIdx.x, by = blockIdx.y;

    float d[2][8][4];
    #pragma unroll
    for (int mt = 0; mt < 2; mt++)
        #pragma unroll
        for (int nt = 0; nt < 8; nt++)
            #pragma unroll
            for (int i = 0; i < 4; i++) d[mt][nt][i] = 0.f;

    // per-thread 16B chunk mapping: f -> r = f>>3 (0..127), c4 = (f&7)*4
    uint32_t dstoff[4];
    const uint32_t *aSrc[4], *wSrc[4];
    uint32_t smbase = (uint32_t)__cvta_generic_to_shared(sm);
    #pragma unroll
    for (int i = 0; i < 4; i++) {
        int f = tid + (i << 8);
        int r = f >> 3, c4 = (f & 7) << 2;
        dstoff[i] = (uint32_t)(r * SKEW + c4) * 4;
        aSrc[i] = A + (size_t)(by * 128 + r) * K + c4;
        wSrc[i] = W + (size_t)(bx * 128 + r) * K + c4;
    }

    auto issue = [&](int k0, int stg) {
        uint32_t b = smbase + (uint32_t)stg * (STG_W * 4);
        #pragma unroll
        for (int i = 0; i < 4; i++) {
            asm volatile("cp.async.cg.shared.global [%0], [%1], 16;"
                         :: "r"(b + dstoff[i]), "l"(aSrc[i] + k0) : "memory");
            asm volatile("cp.async.cg.shared.global [%0], [%1], 16;"
                         :: "r"(b + ASTG_W * 4 + dstoff[i]), "l"(wSrc[i] + k0) : "memory");
        }
        asm volatile("cp.async.commit_group;" ::: "memory");
    };

    issue(0, 0);
    int stage = 0;
    for (int k0 = 0; k0 < K; k0 += 32) {
        bool nxt = (k0 + 32) < K;
        if (nxt) {
            issue(k0 + 32, stage ^ 1);
            asm volatile("cp.async.wait_group 1;" ::: "memory");
        } else {
            asm volatile("cp.async.wait_group 0;" ::: "memory");
        }
        __syncthreads();

        const uint32_t* Ab = sm + stage * STG_W;
        const uint32_t* Wb = Ab + ASTG_W;
        #pragma unroll
        for (int ks = 0; ks < 4; ks++) {
            int kb = ks * 8;
            uint32_t af[2][4];
            #pragma unroll
            for (int mt = 0; mt < 2; mt++) {
                int ar = wm * 32 + mt * 16 + g;
                af[mt][0] = Ab[ar * SKEW + kb + tig];
                af[mt][1] = Ab[(ar + 8) * SKEW + kb + tig];
                af[mt][2] = Ab[ar * SKEW + kb + tig + 4];
                af[mt][3] = Ab[(ar + 8) * SKEW + kb + tig + 4];
            }
            #pragma unroll
            for (int nt = 0; nt < 8; nt++) {
                int bc = wn * 64 + nt * 8 + g;
                uint32_t b0 = Wb[bc * SKEW + kb + tig];
                uint32_t b1 = Wb[bc * SKEW + kb + tig + 4];
                mma_tf32(d[0][nt], af[0], b0, b1);
                mma_tf32(d[1][nt], af[1], b0, b1);
            }
        }
        __syncthreads();   // mma done before next issue overwrites other buffer
        stage ^= 1;
    }

    #pragma unroll
    for (int mt = 0; mt < 2; mt++) {
        int row0 = by * 128 + wm * 32 + mt * 16 + g;
        float rs0 = rowscale ? rowscale[row0] : 1.f;
        float rs1 = rowscale ? rowscale[row0 + 8] : 1.f;
        #pragma unroll
        for (int nt = 0; nt < 8; nt++) {
            int col = bx * 128 + wn * 64 + nt * 8 + tig * 2;
            float b0 = bias[col], b1 = bias[col + 1];
            float v00 = d[mt][nt][0] * rs0 + b0, v01 = d[mt][nt][1] * rs0 + b1;
            float v10 = d[mt][nt][2] * rs1 + b0, v11 = d[mt][nt][3] * rs1 + b1;
            if (relu) {
                v00 = fmaxf(v00, 0.f); v01 = fmaxf(v01, 0.f);
                v10 = fmaxf(v10, 0.f); v11 = fmaxf(v11, 0.f);
            }
            size_t o0 = (size_t)row0 * N + col;
            size_t o1 = (size_t)(row0 + 8) * N + col;
            if (C) {
                *(float2*)(C + o0) = make_float2(v00, v01);
                *(float2*)(C + o1) = make_float2(v10, v11);
            }
            if (Ct) {
                uint2 t0v = make_uint2(f2tf32(v00), f2tf32(v01));
                uint2 t1v = make_uint2(f2tf32(v10), f2tf32(v11));
                *(uint2*)(Ct + o0) = t0v;
                *(uint2*)(Ct + o1) = t1v;
            }
        }
    }
}

// =====================================================================
// Fused flash attention (tf32). Q/K/V are pre-converted tf32 words.
// Writes ctx_t (tf32 words) and optional attn (fp32).
// =====================================================================
#define FQ 0
#define FK 8192
#define FV 16384
#define FP 26624
#define FL_SMEM_WORDS 43008

__global__ __launch_bounds__(256) void flash_tf32_kernel(
    const uint32_t* __restrict__ Q, const uint32_t* __restrict__ Kk,
    const uint32_t* __restrict__ V, const float* __restrict__ mask,
    uint32_t* __restrict__ ctx_t, float* __restrict__ attn, int causal)
{
    extern __shared__ uint32_t sm[];
    uint32_t* Qs = sm + FQ;
    uint32_t* Ks = sm + FK;
    uint32_t* Vs = sm + FV;
    const int tid = threadIdx.x;
    const int lane = tid & 31, warp = tid >> 5;
    const int g = lane >> 2, tig = lane & 3;
    const int bh = blockIdx.y;
    const int b = bh / HH, h = bh % HH;
    const int t0 = blockIdx.x * 128;
    const int wr0 = warp * 16;
    uint32_t* Pw = sm + FP + warp * 2048;

    #pragma unroll
    for (int i = 0; i < 8; i++) {
        int f = tid + (i << 8);
        int r = f >> 4;
        int c4 = (f & 15) << 2;
        int bse = ((c4 >> 3) << 10) + (r << 3) + ((c4 >> 2) & 1);
        uint4 q4 = *(const uint4*)(Q + ((size_t)(t0 + r) * BB + b) * DD + h * HDD + c4);
        Qs[bse + 0] = q4.x; Qs[bse + 2] = q4.y;
        Qs[bse + 4] = q4.z; Qs[bse + 6] = q4.w;
    }

    float mA = -1e30f, mB = -1e30f, lA = 0.f, lB = 0.f;
    float o[8][4];
    #pragma unroll
    for (int nt = 0; nt < 8; nt++)
        #pragma unroll
        for (int i = 0; i < 4; i++) o[nt][i] = 0.f;

    const int pe = ((tig * 2) & 3) * 2 + (tig >> 1);
    const int n_stiles = causal ? (blockIdx.x + 1) : (SSZ / 128);

    for (int is = 0; is < n_stiles; is++) {
        int s0 = is * 128;
        __syncthreads();

        #pragma unroll
        for (int i = 0; i < 8; i++) {
            int f = tid + (i << 8);
            int r = f >> 4;
            int c4 = (f & 15) << 2;
            int bse = ((c4 >> 3) << 10) + (r << 3) + ((c4 >> 2) & 1);
            uint4 k4 = *(const uint4*)(Kk + ((size_t)(s0 + r) * BB + b) * DD + h * HDD + c4);
            Ks[bse + 0] = k4.x; Ks[bse + 2] = k4.y;
            Ks[bse + 4] = k4.z; Ks[bse + 6] = k4.w;
            uint4 v4 = *(const uint4*)(V + ((size_t)(s0 + r) * BB + b) * DD + h * HDD + c4);
            int vb = ((r >> 3) * 640) + ((r & 3) << 1) + ((r >> 2) & 1);
            Vs[vb + (c4 + 0) * 10] = v4.x;
            Vs[vb + (c4 + 1) * 10] = v4.y;
            Vs[vb + (c4 + 2) * 10] = v4.z;
            Vs[vb + (c4 + 3) * 10] = v4.w;
        }
        __syncthreads();

        float s[16][4];
        #pragma unroll
        for (int nt = 0; nt < 16; nt++)
            #pragma unroll
            for (int i = 0; i < 4; i++) s[nt][i] = 0.f;

        #pragma unroll
        for (int ks = 0; ks < 8; ks++) {
            int ab = ks << 10;
            uint2 a0 = *(const uint2*)&Qs[ab + (wr0 + g) * 8 + tig * 2];
            uint2 a1 = *(const uint2*)&Qs[ab + (wr0 + 8 + g) * 8 + tig * 2];
            uint32_t af[4] = {a0.x, a1.x, a0.y, a1.y};
            #pragma unroll
            for (int nt = 0; nt < 16; nt++) {
                uint2 bb = *(const uint2*)&Ks[ab + (nt * 8 + g) * 8 + tig * 2];
                mma_tf32(s[nt], af, bb.x, bb.y);
            }
        }

        const float scale = 0.125f;
        if (causal && is == blockIdx.x) {
            int tAr = t0 + wr0 + g, tBr = tAr + 8;
            #pragma unroll
            for (int nt = 0; nt < 16; nt++) {
                int c = s0 + nt * 8 + tig * 2;
                s[nt][0] = s[nt][0] * scale + mask[(size_t)tAr * TT + c];
                s[nt][1] = s[nt][1] * scale + mask[(size_t)tAr * TT + c + 1];
                s[nt][2] = s[nt][2] * scale + mask[(size_t)tBr * TT + c];
                s[nt][3] = s[nt][3] * scale + mask[(size_t)tBr * TT + c + 1];
            }
        } else {
            #pragma unroll
            for (int nt = 0; nt < 16; nt++)
                #pragma unroll
                for (int i = 0; i < 4; i++) s[nt][i] *= scale;
        }

        float mtA = -1e30f, mtB = -1e30f;
        #pragma unroll
        for (int nt = 0; nt < 16; nt++) {
            mtA = fmaxf(mtA, fmaxf(s[nt][0], s[nt][1]));
            mtB = fmaxf(mtB, fmaxf(s[nt][2], s[nt][3]));
        }
        mtA = fmaxf(mtA, __shfl_xor_sync(0xffffffffu, mtA, 1));
        mtA = fmaxf(mtA, __shfl_xor_sync(0xffffffffu, mtA, 2));
        mtB = fmaxf(mtB, __shfl_xor_sync(0xffffffffu, mtB, 1));
        mtB = fmaxf(mtB, __shfl_xor_sync(0xffffffffu, mtB, 2));

        float mnA = fmaxf(mA, mtA), mnB = fmaxf(mB, mtB);
        float alA = __expf(mA - mnA), alB = __expf(mB - mnB);
        float rsA = 0.f, rsB = 0.f;
        #pragma unroll
        for (int nt = 0; nt < 16; nt++) {
            s[nt][0] = __expf(s[nt][0] - mnA);
            s[nt][1] = __expf(s[nt][1] - mnA);
            s[nt][2] = __expf(s[nt][2] - mnB);
            s[nt][3] = __expf(s[nt][3] - mnB);
            rsA += s[nt][0] + s[nt][1];
            rsB += s[nt][2] + s[nt][3];
        }
        rsA += __shfl_xor_sync(0xffffffffu, rsA, 1);
        rsA += __shfl_xor_sync(0xffffffffu, rsA, 2);
        rsB += __shfl_xor_sync(0xffffffffu, rsB, 1);
        rsB += __shfl_xor_sync(0xffffffffu, rsB, 2);
        lA = lA * alA + rsA; mA = mnA;
        lB = lB * alB + rsB; mB = mnB;

        #pragma unroll
        for (int nt = 0; nt < 8; nt++) {
            o[nt][0] *= alA; o[nt][1] *= alA;
            o[nt][2] *= alB; o[nt][3] *= alB;
        }

        __syncwarp();
        #pragma unroll
        for (int nt = 0; nt < 16; nt++) {
            int base = (nt << 7) + g * 8 + pe;
            Pw[base]          = f2tf32(s[nt][0]);
            Pw[base + 2]      = f2tf32(s[nt][1]);
            Pw[base + 64]     = f2tf32(s[nt][2]);
            Pw[base + 64 + 2] = f2tf32(s[nt][3]);
        }
        __syncwarp();

        #pragma unroll
        for (int ks = 0; ks < 16; ks++) {
            uint2 a0 = *(const uint2*)&Pw[(ks << 7) + g * 8 + tig * 2];
            uint2 a1 = *(const uint2*)&Pw[(ks << 7) + (g + 8) * 8 + tig * 2];
            uint32_t af[4] = {a0.x, a1.x, a0.y, a1.y};
            #pragma unroll
            for (int nt = 0; nt < 8; nt++) {
                uint2 bb = *(const uint2*)&Vs[ks * 640 + (nt * 8 + g) * 10 + tig * 2];
                mma_tf32(o[nt], af, bb.x, bb.y);
            }
        }
    }

    float invA = 1.f / lA, invB = 1.f / lB;
    int tA = t0 + wr0 + g, tB = tA + 8;
    #pragma unroll
    for (int nt = 0; nt < 8; nt++) {
        int hd = nt * 8 + tig * 2;
        float a0 = o[nt][0] * invA, a1 = o[nt][1] * invA;
        float b0 = o[nt][2] * invB, b1 = o[nt][3] * invB;
        *(uint2*)(ctx_t + ((size_t)tA * BB + b) * DD + h * HDD + hd) = make_uint2(f2tf32(a0), f2tf32(a1));
        *(uint2*)(ctx_t + ((size_t)tB * BB + b) * DD + h * HDD + hd) = make_uint2(f2tf32(b0), f2tf32(b1));
        if (attn) {
            *(float2*)(attn + (((size_t)h * BB + b) * TT + tA) * HDD + hd) = make_float2(a0, a1);
            *(float2*)(attn + (((size_t)h * BB + b) * TT + tB) * HDD + hd) = make_float2(b0, b1);
        }
    }
}

// ---------------- fused residual add + layernorm (optional tf32 dual store)
__global__ __launch_bounds__(256) void add_ln_kernel(
    const float* __restrict__ a, const float* __restrict__ r,
    const float* __restrict__ g, const float* __restrict__ be,
    float* __restrict__ o, uint32_t* __restrict__ ot)
{
    size_t row = blockIdx.x;
    int tid = threadIdx.x;
    float4 va = *(const float4*)(a + row * DD + tid * 4);
    float4 vr = *(const float4*)(r + row * DD + tid * 4);
    float x0 = va.x + vr.x, x1 = va.y + vr.y, x2 = va.z + vr.z, x3 = va.w + vr.w;
    float s  = block_sum(x0 + x1 + x2 + x3);
    float mu = s * (1.f / DD);
    float d0 = x0 - mu, d1 = x1 - mu, d2 = x2 - mu, d3 = x3 - mu;
    float sq = block_sum(d0 * d0 + d1 * d1 + d2 * d2 + d3 * d3);
    float inv = rsqrtf(sq * (1.f / DD) + 1e-5f);
    float4 vg = *(const float4*)(g + tid * 4);
    float4 vb = *(const float4*)(be + tid * 4);
    float4 out;
    out.x = d0 * inv * vg.x + vb.x;
    out.y = d1 * inv * vg.y + vb.y;
    out.z = d2 * inv * vg.z + vb.z;
    out.w = d3 * inv * vg.w + vb.w;
    *(float4*)(o + row * DD + tid * 4) = out;
    if (ot) {
        uint4 t;
        t.x = f2tf32(out.x); t.y = f2tf32(out.y);
        t.z = f2tf32(out.z); t.w = f2tf32(out.w);
        *(uint4*)(ot + row * DD + tid * 4) = t;
    }
}

// ---------------- host launch ----------------
extern "C" void kernel_launch(void* const* d_in, const int* in_sizes, int n_in,
                              void* d_out, int out_size)
{
    const float* state = (const float*)d_in[0];
    const float* enc   = (const float*)d_in[1];
    const float* amask = (const float*)d_in[2];
    const int* spad = (const int*)d_in[3];
    const int* epad = (const int*)d_in[4];
    const float *saWq = (const float*)d_in[5],  *sabq = (const float*)d_in[6];
    const float *saWk = (const float*)d_in[7],  *sabk = (const float*)d_in[8];
    const float *saWv = (const float*)d_in[9],  *sabv = (const float*)d_in[10];
    const float *saWo = (const float*)d_in[11], *sabo = (const float*)d_in[12];
    const float *eaWq = (const float*)d_in[13], *eabq = (const float*)d_in[14];
    const float *eaWk = (const float*)d_in[15], *eabk = (const float*)d_in[16];
    const float *eaWv = (const float*)d_in[17], *eabv = (const float*)d_in[18];
    const float *eaWo = (const float*)d_in[19], *eabo = (const float*)d_in[20];
    const float *ln1g = (const float*)d_in[21], *ln1b = (const float*)d_in[22];
    const float *ln2g = (const float*)d_in[23], *ln2b = (const float*)d_in[24];
    const float *ln3g = (const float*)d_in[25], *ln3b = (const float*)d_in[26];
    const float *fc1W = (const float*)d_in[27], *fc1b = (const float*)d_in[28];
    const float *fc2W = (const float*)d_in[29], *fc2b = (const float*)d_in[30];

    uint32_t *state_t, *enc_t, *qt, *kt, *vt, *ctx_t, *x1t, *x2t, *ffn_t, *wtf;
    float *tmp, *x1, *x2, *rss, *rse;
    cudaGetSymbolAddress((void**)&state_t, g_state_t);
    cudaGetSymbolAddress((void**)&enc_t,   g_enc_t);
    cudaGetSymbolAddress((void**)&qt,  g_qt);
    cudaGetSymbolAddress((void**)&kt,  g_kt);
    cudaGetSymbolAddress((void**)&vt,  g_vt);
    cudaGetSymbolAddress((void**)&ctx_t, g_ctx_t);
    cudaGetSymbolAddress((void**)&tmp, g_tmp);
    cudaGetSymbolAddress((void**)&x1,  g_x1);
    cudaGetSymbolAddress((void**)&x1t, g_x1t);
    cudaGetSymbolAddress((void**)&x2,  g_x2);
    cudaGetSymbolAddress((void**)&x2t, g_x2t);
    cudaGetSymbolAddress((void**)&ffn_t, g_ffn_t);
    cudaGetSymbolAddress((void**)&rss, g_rs_self);
    cudaGetSymbolAddress((void**)&rse, g_rs_enc);
    cudaGetSymbolAddress((void**)&wtf, g_wtf);

    const int GSM = STG_W * 2 * 4;          // 73728
    const int FSM = FL_SMEM_WORDS * 4;      // 172032
    cudaFuncSetAttribute(gemm_tf32_kernel,  cudaFuncAttributeMaxDynamicSharedMemorySize, GSM);
    cudaFuncSetAttribute(flash_tf32_kernel, cudaFuncAttributeMaxDynamicSharedMemorySize, FSM);

    float* outx = (float*)d_out;
    float* outa = outx + (size_t)MM * DD;

    // ---- pre-convert weights + input activations to tf32 ----
    const int NW = DD * DD;      // 1M
    const int NF = FFND * DD;    // 4M
    const int NA = MM * DD;      // 4M
    cvt_tf32_kernel<<<NW / 1024, 256>>>(saWq, wtf + WOFF_SAQ, NW);
    cvt_tf32_kernel<<<NW / 1024, 256>>>(saWk, wtf + WOFF_SAK, NW);
    cvt_tf32_kernel<<<NW / 1024, 256>>>(saWv, wtf + WOFF_SAV, NW);
    cvt_tf32_kernel<<<NW / 1024, 256>>>(saWo, wtf + WOFF_SAO, NW);
    cvt_tf32_kernel<<<NW / 1024, 256>>>(eaWq, wtf + WOFF_EAQ, NW);
    cvt_tf32_kernel<<<NW / 1024, 256>>>(eaWk, wtf + WOFF_EAK, NW);
    cvt_tf32_kernel<<<NW / 1024, 256>>>(eaWv, wtf + WOFF_EAV, NW);
    cvt_tf32_kernel<<<NW / 1024, 256>>>(eaWo, wtf + WOFF_EAO, NW);
    cvt_tf32_kernel<<<NF / 1024, 256>>>(fc1W, wtf + WOFF_FC1, NF);
    cvt_tf32_kernel<<<NF / 1024, 256>>>(fc2W, wtf + WOFF_FC2, NF);
    cvt_tf32_kernel<<<NA / 1024, 256>>>(state, state_t, NA);
    cvt_tf32_kernel<<<NA / 1024, 256>>>(enc,   enc_t,   NA);

    expand_mask_kernel<<<(MM + 255) / 256, 256>>>(spad, rss, TT);
    expand_mask_kernel<<<(MM + 255) / 256, 256>>>(epad, rse, SSZ);

    dim3 gP(DD / 128, MM / 128);
    dim3 gF1(FFND / 128, MM / 128);
    dim3 gFl(TT / 128, BB * HH);

    // ---- self-attention ----
    gemm_tf32_kernel<<<gP, 256, GSM>>>(state_t, wtf + WOFF_SAQ, sabq, nullptr, nullptr, qt, MM, DD, DD, 0);
    gemm_tf32_kernel<<<gP, 256, GSM>>>(state_t, wtf + WOFF_SAK, sabk, rss,     nullptr, kt, MM, DD, DD, 0);
    gemm_tf32_kernel<<<gP, 256, GSM>>>(state_t, wtf + WOFF_SAV, sabv, nullptr, nullptr, vt, MM, DD, DD, 0);
    flash_tf32_kernel<<<gFl, 256, FSM>>>(qt, kt, vt, amask, ctx_t, nullptr, 1);
    gemm_tf32_kernel<<<gP, 256, GSM>>>(ctx_t, wtf + WOFF_SAO, sabo, nullptr, tmp, nullptr, MM, DD, DD, 0);
    add_ln_kernel<<<MM, 256>>>(tmp, state, ln1g, ln1b, x1, x1t);

    // ---- encoder-decoder attention ----
    gemm_tf32_kernel<<<gP, 256, GSM>>>(x1t,   wtf + WOFF_EAQ, eabq, nullptr, nullptr, qt, MM, DD, DD, 0);
    gemm_tf32_kernel<<<gP, 256, GSM>>>(enc_t, wtf + WOFF_EAK, eabk, rse,     nullptr, kt, MM, DD, DD, 0);
    gemm_tf32_kernel<<<gP, 256, GSM>>>(enc_t, wtf + WOFF_EAV, eabv, nullptr, nullptr, vt, MM, DD, DD, 0);
    flash_tf32_kernel<<<gFl, 256, FSM>>>(qt, kt, vt, nullptr, ctx_t, outa, 0);
    gemm_tf32_kernel<<<gP, 256, GSM>>>(ctx_t, wtf + WOFF_EAO, eabo, nullptr, tmp, nullptr, MM, DD, DD, 0);
    add_ln_kernel<<<MM, 256>>>(tmp, x1, ln2g, ln2b, x2, x2t);

    // ---- FFN ----
    gemm_tf32_kernel<<<gF1, 256, GSM>>>(x2t,   wtf + WOFF_FC1, fc1b, nullptr, nullptr, ffn_t, MM, FFND, DD, 1);
    gemm_tf32_kernel<<<gP, 256, GSM>>>(ffn_t, wtf + WOFF_FC2, fc2b, nullptr, tmp, nullptr, MM, DD, FFND, 0);
    add_ln_kernel<<<MM, 256>>>(tmp, x2, ln3g, ln3b, outx, nullptr);
}

// round 10
// speedup vs baseline: 1.5785x; 1.0139x over previous
#include <cuda_runtime.h>
#include <math.h>
#include <stdint.h>

#define TT   1024
#define SSZ  1024
#define BB   4
#define DD   1024
#define HH   16
#define HDD  64
#define FFND 4096
#define MM   (TT*BB)

// ---------------- scratch (device globals; no allocs allowed) ----------------
__device__ uint32_t g_state_t[MM*DD];
__device__ uint32_t g_enc_t[MM*DD];
__device__ uint32_t g_qt[MM*DD];
__device__ uint32_t g_kt[MM*DD];
__device__ uint32_t g_vt[MM*DD];
__device__ uint32_t g_ctx_t[MM*DD];
__device__ float    g_tmp[MM*DD];
__device__ float    g_x1[MM*DD];
__device__ uint32_t g_x1t[MM*DD];
__device__ float    g_x2[MM*DD];
__device__ uint32_t g_x2t[MM*DD];
__device__ uint32_t g_ffn_t[(size_t)MM*FFND];
__device__ float    g_rs_self[MM];
__device__ float    g_rs_enc[MM];
__device__ uint32_t g_wtf[16*1024*1024];

#define WOFF_SAQ  (0*1048576)
#define WOFF_SAK  (1*1048576)
#define WOFF_SAV  (2*1048576)
#define WOFF_SAO  (3*1048576)
#define WOFF_EAQ  (4*1048576)
#define WOFF_EAK  (5*1048576)
#define WOFF_EAV  (6*1048576)
#define WOFF_EAO  (7*1048576)
#define WOFF_FC1  (8*1048576)
#define WOFF_FC2  (12*1048576)

// ---------------- helpers ----------------
__device__ __forceinline__ float block_sum(float v) {
    __shared__ float sh[8];
    __shared__ float res;
    int lane = threadIdx.x & 31, w = threadIdx.x >> 5;
    #pragma unroll
    for (int o = 16; o > 0; o >>= 1) v += __shfl_xor_sync(0xffffffffu, v, o);
    __syncthreads();
    if (lane == 0) sh[w] = v;
    __syncthreads();
    if (threadIdx.x == 0) {
        float t = 0.f;
        #pragma unroll
        for (int i = 0; i < 8; i++) t += sh[i];
        res = t;
    }
    __syncthreads();
    return res;
}

__device__ __forceinline__ uint32_t f2tf32(float x) {
    uint32_t u;
    asm("cvt.rna.tf32.f32 %0, %1;" : "=r"(u) : "f"(x));
    return u;
}

__device__ __forceinline__ void mma_tf32(float* d, const uint32_t* a, uint32_t b0, uint32_t b1) {
    asm volatile(
        "mma.sync.aligned.m16n8k8.row.col.f32.tf32.tf32.f32 "
        "{%0,%1,%2,%3}, {%4,%5,%6,%7}, {%8,%9}, {%0,%1,%2,%3};"
        : "+f"(d[0]), "+f"(d[1]), "+f"(d[2]), "+f"(d[3])
        : "r"(a[0]), "r"(a[1]), "r"(a[2]), "r"(a[3]), "r"(b0), "r"(b1));
}

__global__ void expand_mask_kernel(const int* __restrict__ mask,
                                   float* __restrict__ rowscale, int L) {
    int r = blockIdx.x * blockDim.x + threadIdx.x;
    if (r < L * BB) {
        int pos = r / BB, b = r % BB;
        rowscale[r] = mask[b * L + pos] ? 0.f : 1.f;
    }
}

// ---------------- fused fp32 -> tf32 conversion over 12 segments ----------------
struct CvtJobs {
    const float* src[12];
    uint32_t*    dst[12];
    int          n[12];
};

__global__ __launch_bounds__(256) void cvt_all_kernel(CvtJobs jobs)
{
    int seg = blockIdx.y;
    int n = jobs.n[seg];
    int i = (blockIdx.x * blockDim.x + threadIdx.x) * 4;
    if (i < n) {
        float4 v = *(const float4*)(jobs.src[seg] + i);
        uint4 o;
        o.x = f2tf32(v.x); o.y = f2tf32(v.y);
        o.z = f2tf32(v.z); o.w = f2tf32(v.w);
        *(uint4*)(jobs.dst[seg] + i) = o;
    }
}

// =====================================================================
// TF32 GEMM (mma.sync): C[M,N] = A[M,K] @ W[N,K]^T (+bias, rowscale, relu).
// CTA tile 256x128x32, 256 thr (8 warps, 4m x 2n, warp tile 64x64).
// cp.async double-buffered SKEW-36 smem.
// smem/stage: A 256*36 + B 128*36 = 13824 words; total 110592 B.
// =====================================================================
#define SKEW 36
#define A_W  (256*SKEW)          // 9216 words
#define B_W  (128*SKEW)          // 4608 words
#define STG_W (A_W + B_W)        // 13824 words per stage
#define GSMB (2*STG_W*4)         // 110592 bytes

__global__ __launch_bounds__(256) void gemm_tf32_kernel(
    const uint32_t* __restrict__ A, const uint32_t* __restrict__ W,
    const float* __restrict__ bias, const float* __restrict__ rowscale,
    float* __restrict__ C, uint32_t* __restrict__ Ct,
    int M, int N, int K, int relu)
{
    extern __shared__ uint32_t sm[];
    const int tid = threadIdx.x;
    const int lane = tid & 31, warp = tid >> 5;
    const int wm = warp & 3, wn = warp >> 2;
    const int g = lane >> 2, tig = lane & 3;
    const int bx = blockIdx.x, by = blockIdx.y;

    float d[4][8][4];
    #pragma unroll
    for (int mt = 0; mt < 4; mt++)
        #pragma unroll
        for (int nt = 0; nt < 8; nt++)
            #pragma unroll
            for (int i = 0; i < 4; i++) d[mt][nt][i] = 0.f;

    uint32_t smbase = (uint32_t)__cvta_generic_to_shared(sm);
    // A tile: 256 rows x 8 16B-chunks -> 8 per thread; B: 128 x 8 -> 4 per thread
    uint32_t dstA[8], dstB[4];
    const uint32_t *aS[8], *wS[4];
    #pragma unroll
    for (int i = 0; i < 8; i++) {
        int f = tid + (i << 8);
        int r = f >> 3, c4 = (f & 7) << 2;
        dstA[i] = (uint32_t)(r * SKEW + c4) * 4;
        aS[i] = A + (size_t)(by * 256 + r) * K + c4;
    }
    #pragma unroll
    for (int i = 0; i < 4; i++) {
        int f = tid + (i << 8);
        int r = f >> 3, c4 = (f & 7) << 2;
        dstB[i] = (uint32_t)(A_W + r * SKEW + c4) * 4;
        wS[i] = W + (size_t)(bx * 128 + r) * K + c4;
    }

    auto issue = [&](int k0, int stg) {
        uint32_t b = smbase + (uint32_t)stg * (STG_W * 4);
        #pragma unroll
        for (int i = 0; i < 8; i++)
            asm volatile("cp.async.cg.shared.global [%0], [%1], 16;"
                         :: "r"(b + dstA[i]), "l"(aS[i] + k0) : "memory");
        #pragma unroll
        for (int i = 0; i < 4; i++)
            asm volatile("cp.async.cg.shared.global [%0], [%1], 16;"
                         :: "r"(b + dstB[i]), "l"(wS[i] + k0) : "memory");
        asm volatile("cp.async.commit_group;" ::: "memory");
    };

    issue(0, 0);
    int stage = 0;
    for (int k0 = 0; k0 < K; k0 += 32) {
        bool nxt = (k0 + 32) < K;
        if (nxt) {
            issue(k0 + 32, stage ^ 1);
            asm volatile("cp.async.wait_group 1;" ::: "memory");
        } else {
            asm volatile("cp.async.wait_group 0;" ::: "memory");
        }
        __syncthreads();

        const uint32_t* Ab = sm + stage * STG_W;
        const uint32_t* Wb = Ab + A_W;
        #pragma unroll
        for (int ks = 0; ks < 4; ks++) {
            int kb = ks * 8;
            uint32_t af[4][4];
            #pragma unroll
            for (int mt = 0; mt < 4; mt++) {
                int ar = wm * 64 + mt * 16 + g;
                af[mt][0] = Ab[ar * SKEW + kb + tig];
                af[mt][1] = Ab[(ar + 8) * SKEW + kb + tig];
                af[mt][2] = Ab[ar * SKEW + kb + tig + 4];
                af[mt][3] = Ab[(ar + 8) * SKEW + kb + tig + 4];
            }
            #pragma unroll
            for (int nt = 0; nt < 8; nt++) {
                int bc = wn * 64 + nt * 8 + g;
                uint32_t b0 = Wb[bc * SKEW + kb + tig];
                uint32_t b1 = Wb[bc * SKEW + kb + tig + 4];
                #pragma unroll
                for (int mt = 0; mt < 4; mt++)
                    mma_tf32(d[mt][nt], af[mt], b0, b1);
            }
        }
        __syncthreads();
        stage ^= 1;
    }

    #pragma unroll
    for (int mt = 0; mt < 4; mt++) {
        int row0 = by * 256 + wm * 64 + mt * 16 + g;
        float rs0 = rowscale ? rowscale[row0] : 1.f;
        float rs1 = rowscale ? rowscale[row0 + 8] : 1.f;
        #pragma unroll
        for (int nt = 0; nt < 8; nt++) {
            int col = bx * 128 + wn * 64 + nt * 8 + tig * 2;
            float b0 = bias[col], b1 = bias[col + 1];
            float v00 = d[mt][nt][0] * rs0 + b0, v01 = d[mt][nt][1] * rs0 + b1;
            float v10 = d[mt][nt][2] * rs1 + b0, v11 = d[mt][nt][3] * rs1 + b1;
            if (relu) {
                v00 = fmaxf(v00, 0.f); v01 = fmaxf(v01, 0.f);
                v10 = fmaxf(v10, 0.f); v11 = fmaxf(v11, 0.f);
            }
            size_t o0 = (size_t)row0 * N + col;
            size_t o1 = (size_t)(row0 + 8) * N + col;
            if (C) {
                *(float2*)(C + o0) = make_float2(v00, v01);
                *(float2*)(C + o1) = make_float2(v10, v11);
            }
            if (Ct) {
                *(uint2*)(Ct + o0) = make_uint2(f2tf32(v00), f2tf32(v01));
                *(uint2*)(Ct + o1) = make_uint2(f2tf32(v10), f2tf32(v11));
            }
        }
    }
}

// =====================================================================
// Fused flash attention (tf32, mma.sync) — unchanged from round 8.
// =====================================================================
#define FQ 0
#define FK 8192
#define FV 16384
#define FP 26624
#define FL_SMEM_WORDS 43008

__global__ __launch_bounds__(256) void flash_tf32_kernel(
    const uint32_t* __restrict__ Q, const uint32_t* __restrict__ Kk,
    const uint32_t* __restrict__ V, const float* __restrict__ mask,
    uint32_t* __restrict__ ctx_t, float* __restrict__ attn, int causal)
{
    extern __shared__ uint32_t sm[];
    uint32_t* Qs = sm + FQ;
    uint32_t* Ks = sm + FK;
    uint32_t* Vs = sm + FV;
    const int tid = threadIdx.x;
    const int lane = tid & 31, warp = tid >> 5;
    const int g = lane >> 2, tig = lane & 3;
    const int bh = blockIdx.y;
    const int b = bh / HH, h = bh % HH;
    const int t0 = blockIdx.x * 128;
    const int wr0 = warp * 16;
    uint32_t* Pw = sm + FP + warp * 2048;

    #pragma unroll
    for (int i = 0; i < 8; i++) {
        int f = tid + (i << 8);
        int r = f >> 4;
        int c4 = (f & 15) << 2;
        int bse = ((c4 >> 3) << 10) + (r << 3) + ((c4 >> 2) & 1);
        uint4 q4 = *(const uint4*)(Q + ((size_t)(t0 + r) * BB + b) * DD + h * HDD + c4);
        Qs[bse + 0] = q4.x; Qs[bse + 2] = q4.y;
        Qs[bse + 4] = q4.z; Qs[bse + 6] = q4.w;
    }

    float mA = -1e30f, mB = -1e30f, lA = 0.f, lB = 0.f;
    float o[8][4];
    #pragma unroll
    for (int nt = 0; nt < 8; nt++)
        #pragma unroll
        for (int i = 0; i < 4; i++) o[nt][i] = 0.f;

    const int pe = ((tig * 2) & 3) * 2 + (tig >> 1);
    const int n_stiles = causal ? (blockIdx.x + 1) : (SSZ / 128);

    for (int is = 0; is < n_stiles; is++) {
        int s0 = is * 128;
        __syncthreads();

        #pragma unroll
        for (int i = 0; i < 8; i++) {
            int f = tid + (i << 8);
            int r = f >> 4;
            int c4 = (f & 15) << 2;
            int bse = ((c4 >> 3) << 10) + (r << 3) + ((c4 >> 2) & 1);
            uint4 k4 = *(const uint4*)(Kk + ((size_t)(s0 + r) * BB + b) * DD + h * HDD + c4);
            Ks[bse + 0] = k4.x; Ks[bse + 2] = k4.y;
            Ks[bse + 4] = k4.z; Ks[bse + 6] = k4.w;
            uint4 v4 = *(const uint4*)(V + ((size_t)(s0 + r) * BB + b) * DD + h * HDD + c4);
            int vb = ((r >> 3) * 640) + ((r & 3) << 1) + ((r >> 2) & 1);
            Vs[vb + (c4 + 0) * 10] = v4.x;
            Vs[vb + (c4 + 1) * 10] = v4.y;
            Vs[vb + (c4 + 2) * 10] = v4.z;
            Vs[vb + (c4 + 3) * 10] = v4.w;
        }
        __syncthreads();

        float s[16][4];
        #pragma unroll
        for (int nt = 0; nt < 16; nt++)
            #pragma unroll
            for (int i = 0; i < 4; i++) s[nt][i] = 0.f;

        #pragma unroll
        for (int ks = 0; ks < 8; ks++) {
            int ab = ks << 10;
            uint2 a0 = *(const uint2*)&Qs[ab + (wr0 + g) * 8 + tig * 2];
            uint2 a1 = *(const uint2*)&Qs[ab + (wr0 + 8 + g) * 8 + tig * 2];
            uint32_t af[4] = {a0.x, a1.x, a0.y, a1.y};
            #pragma unroll
            for (int nt = 0; nt < 16; nt++) {
                uint2 bb = *(const uint2*)&Ks[ab + (nt * 8 + g) * 8 + tig * 2];
                mma_tf32(s[nt], af, bb.x, bb.y);
            }
        }

        const float scale = 0.125f;
        if (causal && is == blockIdx.x) {
            int tAr = t0 + wr0 + g, tBr = tAr + 8;
            #pragma unroll
            for (int nt = 0; nt < 16; nt++) {
                int c = s0 + nt * 8 + tig * 2;
                s[nt][0] = s[nt][0] * scale + mask[(size_t)tAr * TT + c];
                s[nt][1] = s[nt][1] * scale + mask[(size_t)tAr * TT + c + 1];
                s[nt][2] = s[nt][2] * scale + mask[(size_t)tBr * TT + c];
                s[nt][3] = s[nt][3] * scale + mask[(size_t)tBr * TT + c + 1];
            }
        } else {
            #pragma unroll
            for (int nt = 0; nt < 16; nt++)
                #pragma unroll
                for (int i = 0; i < 4; i++) s[nt][i] *= scale;
        }

        float mtA = -1e30f, mtB = -1e30f;
        #pragma unroll
        for (int nt = 0; nt < 16; nt++) {
            mtA = fmaxf(mtA, fmaxf(s[nt][0], s[nt][1]));
            mtB = fmaxf(mtB, fmaxf(s[nt][2], s[nt][3]));
        }
        mtA = fmaxf(mtA, __shfl_xor_sync(0xffffffffu, mtA, 1));
        mtA = fmaxf(mtA, __shfl_xor_sync(0xffffffffu, mtA, 2));
        mtB = fmaxf(mtB, __shfl_xor_sync(0xffffffffu, mtB, 1));
        mtB = fmaxf(mtB, __shfl_xor_sync(0xffffffffu, mtB, 2));

        float mnA = fmaxf(mA, mtA), mnB = fmaxf(mB, mtB);
        float alA = __expf(mA - mnA), alB = __expf(mB - mnB);
        float rsA = 0.f, rsB = 0.f;
        #pragma unroll
        for (int nt = 0; nt < 16; nt++) {
            s[nt][0] = __expf(s[nt][0] - mnA);
            s[nt][1] = __expf(s[nt][1] - mnA);
            s[nt][2] = __expf(s[nt][2] - mnB);
            s[nt][3] = __expf(s[nt][3] - mnB);
            rsA += s[nt][0] + s[nt][1];
            rsB += s[nt][2] + s[nt][3];
        }
        rsA += __shfl_xor_sync(0xffffffffu, rsA, 1);
        rsA += __shfl_xor_sync(0xffffffffu, rsA, 2);
        rsB += __shfl_xor_sync(0xffffffffu, rsB, 1);
        rsB += __shfl_xor_sync(0xffffffffu, rsB, 2);
        lA = lA * alA + rsA; mA = mnA;
        lB = lB * alB + rsB; mB = mnB;

        #pragma unroll
        for (int nt = 0; nt < 8; nt++) {
            o[nt][0] *= alA; o[nt][1] *= alA;
            o[nt][2] *= alB; o[nt][3] *= alB;
        }

        __syncwarp();
        #pragma unroll
        for (int nt = 0; nt < 16; nt++) {
            int base = (nt << 7) + g * 8 + pe;
            Pw[base]          = f2tf32(s[nt][0]);
            Pw[base + 2]      = f2tf32(s[nt][1]);
            Pw[base + 64]     = f2tf32(s[nt][2]);
            Pw[base + 64 + 2] = f2tf32(s[nt][3]);
        }
        __syncwarp();

        #pragma unroll
        for (int ks = 0; ks < 16; ks++) {
            uint2 a0 = *(const uint2*)&Pw[(ks << 7) + g * 8 + tig * 2];
            uint2 a1 = *(const uint2*)&Pw[(ks << 7) + (g + 8) * 8 + tig * 2];
            uint32_t af[4] = {a0.x, a1.x, a0.y, a1.y};
            #pragma unroll
            for (int nt = 0; nt < 8; nt++) {
                uint2 bb = *(const uint2*)&Vs[ks * 640 + (nt * 8 + g) * 10 + tig * 2];
                mma_tf32(o[nt], af, bb.x, bb.y);
            }
        }
    }

    float invA = 1.f / lA, invB = 1.f / lB;
    int tA = t0 + wr0 + g, tB = tA + 8;
    #pragma unroll
    for (int nt = 0; nt < 8; nt++) {
        int hd = nt * 8 + tig * 2;
        float a0 = o[nt][0] * invA, a1 = o[nt][1] * invA;
        float b0 = o[nt][2] * invB, b1 = o[nt][3] * invB;
        *(uint2*)(ctx_t + ((size_t)tA * BB + b) * DD + h * HDD + hd) = make_uint2(f2tf32(a0), f2tf32(a1));
        *(uint2*)(ctx_t + ((size_t)tB * BB + b) * DD + h * HDD + hd) = make_uint2(f2tf32(b0), f2tf32(b1));
        if (attn) {
            *(float2*)(attn + (((size_t)h * BB + b) * TT + tA) * HDD + hd) = make_float2(a0, a1);
            *(float2*)(attn + (((size_t)h * BB + b) * TT + tB) * HDD + hd) = make_float2(b0, b1);
        }
    }
}

// ---------------- fused residual add + layernorm (optional tf32 dual store)
__global__ __launch_bounds__(256) void add_ln_kernel(
    const float* __restrict__ a, const float* __restrict__ r,
    const float* __restrict__ g, const float* __restrict__ be,
    float* __restrict__ o, uint32_t* __restrict__ ot)
{
    size_t row = blockIdx.x;
    int tid = threadIdx.x;
    float4 va = *(const float4*)(a + row * DD + tid * 4);
    float4 vr = *(const float4*)(r + row * DD + tid * 4);
    float x0 = va.x + vr.x, x1 = va.y + vr.y, x2 = va.z + vr.z, x3 = va.w + vr.w;
    float s  = block_sum(x0 + x1 + x2 + x3);
    float mu = s * (1.f / DD);
    float d0 = x0 - mu, d1 = x1 - mu, d2 = x2 - mu, d3 = x3 - mu;
    float sq = block_sum(d0 * d0 + d1 * d1 + d2 * d2 + d3 * d3);
    float inv = rsqrtf(sq * (1.f / DD) + 1e-5f);
    float4 vg = *(const float4*)(g + tid * 4);
    float4 vb = *(const float4*)(be + tid * 4);
    float4 out;
    out.x = d0 * inv * vg.x + vb.x;
    out.y = d1 * inv * vg.y + vb.y;
    out.z = d2 * inv * vg.z + vb.z;
    out.w = d3 * inv * vg.w + vb.w;
    *(float4*)(o + row * DD + tid * 4) = out;
    if (ot) {
        uint4 t;
        t.x = f2tf32(out.x); t.y = f2tf32(out.y);
        t.z = f2tf32(out.z); t.w = f2tf32(out.w);
        *(uint4*)(ot + row * DD + tid * 4) = t;
    }
}

// ---------------- host launch ----------------
extern "C" void kernel_launch(void* const* d_in, const int* in_sizes, int n_in,
                              void* d_out, int out_size)
{
    const float* state = (const float*)d_in[0];
    const float* enc   = (const float*)d_in[1];
    const float* amask = (const float*)d_in[2];
    const int* spad = (const int*)d_in[3];
    const int* epad = (const int*)d_in[4];
    const float *saWq = (const float*)d_in[5],  *sabq = (const float*)d_in[6];
    const float *saWk = (const float*)d_in[7],  *sabk = (const float*)d_in[8];
    const float *saWv = (const float*)d_in[9],  *sabv = (const float*)d_in[10];
    const float *saWo = (const float*)d_in[11], *sabo = (const float*)d_in[12];
    const float *eaWq = (const float*)d_in[13], *eabq = (const float*)d_in[14];
    const float *eaWk = (const float*)d_in[15], *eabk = (const float*)d_in[16];
    const float *eaWv = (const float*)d_in[17], *eabv = (const float*)d_in[18];
    const float *eaWo = (const float*)d_in[19], *eabo = (const float*)d_in[20];
    const float *ln1g = (const float*)d_in[21], *ln1b = (const float*)d_in[22];
    const float *ln2g = (const float*)d_in[23], *ln2b = (const float*)d_in[24];
    const float *ln3g = (const float*)d_in[25], *ln3b = (const float*)d_in[26];
    const float *fc1W = (const float*)d_in[27], *fc1b = (const float*)d_in[28];
    const float *fc2W = (const float*)d_in[29], *fc2b = (const float*)d_in[30];

    uint32_t *state_t, *enc_t, *qt, *kt, *vt, *ctx_t, *x1t, *x2t, *ffn_t, *wtf;
    float *tmp, *x1, *x2, *rss, *rse;
    cudaGetSymbolAddress((void**)&state_t, g_state_t);
    cudaGetSymbolAddress((void**)&enc_t,   g_enc_t);
    cudaGetSymbolAddress((void**)&qt,  g_qt);
    cudaGetSymbolAddress((void**)&kt,  g_kt);
    cudaGetSymbolAddress((void**)&vt,  g_vt);
    cudaGetSymbolAddress((void**)&ctx_t, g_ctx_t);
    cudaGetSymbolAddress((void**)&tmp, g_tmp);
    cudaGetSymbolAddress((void**)&x1,  g_x1);
    cudaGetSymbolAddress((void**)&x1t, g_x1t);
    cudaGetSymbolAddress((void**)&x2,  g_x2);
    cudaGetSymbolAddress((void**)&x2t, g_x2t);
    cudaGetSymbolAddress((void**)&ffn_t, g_ffn_t);
    cudaGetSymbolAddress((void**)&rss, g_rs_self);
    cudaGetSymbolAddress((void**)&rse, g_rs_enc);
    cudaGetSymbolAddress((void**)&wtf, g_wtf);

    const int FSM = FL_SMEM_WORDS * 4;
    cudaFuncSetAttribute(gemm_tf32_kernel,  cudaFuncAttributeMaxDynamicSharedMemorySize, GSMB);
    cudaFuncSetAttribute(flash_tf32_kernel, cudaFuncAttributeMaxDynamicSharedMemorySize, FSM);

    float* outx = (float*)d_out;
    float* outa = outx + (size_t)MM * DD;

    // ---- pre-convert weights + input activations (one fused kernel) ----
    const int NW = DD * DD;      // 1M
    const int NF = FFND * DD;    // 4M
    const int NA = MM * DD;      // 4M
    CvtJobs jobs;
    jobs.src[0] = saWq; jobs.dst[0] = wtf + WOFF_SAQ; jobs.n[0] = NW;
    jobs.src[1] = saWk; jobs.dst[1] = wtf + WOFF_SAK; jobs.n[1] = NW;
    jobs.src[2] = saWv; jobs.dst[2] = wtf + WOFF_SAV; jobs.n[2] = NW;
    jobs.src[3] = saWo; jobs.dst[3] = wtf + WOFF_SAO; jobs.n[3] = NW;
    jobs.src[4] = eaWq; jobs.dst[4] = wtf + WOFF_EAQ; jobs.n[4] = NW;
    jobs.src[5] = eaWk; jobs.dst[5] = wtf + WOFF_EAK; jobs.n[5] = NW;
    jobs.src[6] = eaWv; jobs.dst[6] = wtf + WOFF_EAV; jobs.n[6] = NW;
    jobs.src[7] = eaWo; jobs.dst[7] = wtf + WOFF_EAO; jobs.n[7] = NW;
    jobs.src[8] = fc1W; jobs.dst[8] = wtf + WOFF_FC1; jobs.n[8] = NF;
    jobs.src[9] = fc2W; jobs.dst[9] = wtf + WOFF_FC2; jobs.n[9] = NF;
    jobs.src[10] = state; jobs.dst[10] = state_t; jobs.n[10] = NA;
    jobs.src[11] = enc;   jobs.dst[11] = enc_t;   jobs.n[11] = NA;
    cvt_all_kernel<<<dim3(NF / 1024, 12), 256>>>(jobs);

    expand_mask_kernel<<<(MM + 255) / 256, 256>>>(spad, rss, TT);
    expand_mask_kernel<<<(MM + 255) / 256, 256>>>(epad, rse, SSZ);

    dim3 gP(DD / 128, MM / 256);        // (8, 16) = 128 CTAs
    dim3 gF1(FFND / 128, MM / 256);     // (32, 16)
    dim3 gFl(TT / 128, BB * HH);

    // ---- self-attention ----
    gemm_tf32_kernel<<<gP, 256, GSMB>>>(state_t, wtf + WOFF_SAQ, sabq, nullptr, nullptr, qt, MM, DD, DD, 0);
    gemm_tf32_kernel<<<gP, 256, GSMB>>>(state_t, wtf + WOFF_SAK, sabk, rss,     nullptr, kt, MM, DD, DD, 0);
    gemm_tf32_kernel<<<gP, 256, GSMB>>>(state_t, wtf + WOFF_SAV, sabv, nullptr, nullptr, vt, MM, DD, DD, 0);
    flash_tf32_kernel<<<gFl, 256, FSM>>>(qt, kt, vt, amask, ctx_t, nullptr, 1);
    gemm_tf32_kernel<<<gP, 256, GSMB>>>(ctx_t, wtf + WOFF_SAO, sabo, nullptr, tmp, nullptr, MM, DD, DD, 0);
    add_ln_kernel<<<MM, 256>>>(tmp, state, ln1g, ln1b, x1, x1t);

    // ---- encoder-decoder attention ----
    gemm_tf32_kernel<<<gP, 256, GSMB>>>(x1t,   wtf + WOFF_EAQ, eabq, nullptr, nullptr, qt, MM, DD, DD, 0);
    gemm_tf32_kernel<<<gP, 256, GSMB>>>(enc_t, wtf + WOFF_EAK, eabk, rse,     nullptr, kt, MM, DD, DD, 0);
    gemm_tf32_kernel<<<gP, 256, GSMB>>>(enc_t, wtf + WOFF_EAV, eabv, nullptr, nullptr, vt, MM, DD, DD, 0);
    flash_tf32_kernel<<<gFl, 256, FSM>>>(qt, kt, vt, nullptr, ctx_t, outa, 0);
    gemm_tf32_kernel<<<gP, 256, GSMB>>>(ctx_t, wtf + WOFF_EAO, eabo, nullptr, tmp, nullptr, MM, DD, DD, 0);
    add_ln_kernel<<<MM, 256>>>(tmp, x1, ln2g, ln2b, x2, x2t);

    // ---- FFN ----
    gemm_tf32_kernel<<<gF1, 256, GSMB>>>(x2t,   wtf + WOFF_FC1, fc1b, nullptr, nullptr, ffn_t, MM, FFND, DD, 1);
    gemm_tf32_kernel<<<gP, 256, GSMB>>>(ffn_t, wtf + WOFF_FC2, fc2b, nullptr, tmp, nullptr, MM, DD, FFND, 0);
    add_ln_kernel<<<MM, 256>>>(tmp, x2, ln3g, ln3b, outx, nullptr);
}

// round 11
// speedup vs baseline: 1.5803x; 1.0011x over previous
#include <cuda_runtime.h>
#include <math.h>
#include <stdint.h>

#define TT   1024
#define SSZ  1024
#define BB   4
#define DD   1024
#define HH   16
#define HDD  64
#define FFND 4096
#define MM   (TT*BB)

// ---------------- scratch (device globals; no allocs allowed) ----------------
__device__ uint32_t g_state_t[MM*DD];
__device__ uint32_t g_enc_t[MM*DD];
__device__ uint32_t g_qt[MM*DD];
__device__ uint32_t g_kt[MM*DD];
__device__ uint32_t g_vt[MM*DD];
__device__ uint32_t g_ctx_t[MM*DD];
__device__ float    g_tmp[MM*DD];
__device__ float    g_x1[MM*DD];
__device__ uint32_t g_x1t[MM*DD];
__device__ float    g_x2[MM*DD];
__device__ uint32_t g_x2t[MM*DD];
__device__ uint32_t g_ffn_t[(size_t)MM*FFND];
__device__ float    g_rs_self[MM];
__device__ float    g_rs_enc[MM];
__device__ uint32_t g_wtf[16*1024*1024];

#define WOFF_SAQ  (0*1048576)
#define WOFF_SAK  (1*1048576)
#define WOFF_SAV  (2*1048576)
#define WOFF_SAO  (3*1048576)
#define WOFF_EAQ  (4*1048576)
#define WOFF_EAK  (5*1048576)
#define WOFF_EAV  (6*1048576)
#define WOFF_EAO  (7*1048576)
#define WOFF_FC1  (8*1048576)
#define WOFF_FC2  (12*1048576)

// ---------------- helpers ----------------
__device__ __forceinline__ float block_sum(float v) {
    __shared__ float sh[8];
    __shared__ float res;
    int lane = threadIdx.x & 31, w = threadIdx.x >> 5;
    #pragma unroll
    for (int o = 16; o > 0; o >>= 1) v += __shfl_xor_sync(0xffffffffu, v, o);
    __syncthreads();
    if (lane == 0) sh[w] = v;
    __syncthreads();
    if (threadIdx.x == 0) {
        float t = 0.f;
        #pragma unroll
        for (int i = 0; i < 8; i++) t += sh[i];
        res = t;
    }
    __syncthreads();
    return res;
}

__device__ __forceinline__ uint32_t f2tf32(float x) {
    uint32_t u;
    asm("cvt.rna.tf32.f32 %0, %1;" : "=r"(u) : "f"(x));
    return u;
}

__device__ __forceinline__ void mma_tf32(float* d, const uint32_t* a, uint32_t b0, uint32_t b1) {
    asm volatile(
        "mma.sync.aligned.m16n8k8.row.col.f32.tf32.tf32.f32 "
        "{%0,%1,%2,%3}, {%4,%5,%6,%7}, {%8,%9}, {%0,%1,%2,%3};"
        : "+f"(d[0]), "+f"(d[1]), "+f"(d[2]), "+f"(d[3])
        : "r"(a[0]), "r"(a[1]), "r"(a[2]), "r"(a[3]), "r"(b0), "r"(b1));
}

__global__ void expand_mask_kernel(const int* __restrict__ mask,
                                   float* __restrict__ rowscale, int L) {
    int r = blockIdx.x * blockDim.x + threadIdx.x;
    if (r < L * BB) {
        int pos = r / BB, b = r % BB;
        rowscale[r] = mask[b * L + pos] ? 0.f : 1.f;
    }
}

// ---------------- fused fp32 -> tf32 conversion over 12 segments ----------------
struct CvtJobs {
    const float* src[12];
    uint32_t*    dst[12];
    int          n[12];
};

__global__ __launch_bounds__(256) void cvt_all_kernel(CvtJobs jobs)
{
    int seg = blockIdx.y;
    int n = jobs.n[seg];
    int i = (blockIdx.x * blockDim.x + threadIdx.x) * 4;
    if (i < n) {
        float4 v = *(const float4*)(jobs.src[seg] + i);
        uint4 o;
        o.x = f2tf32(v.x); o.y = f2tf32(v.y);
        o.z = f2tf32(v.z); o.w = f2tf32(v.w);
        *(uint4*)(jobs.dst[seg] + i) = o;
    }
}

// =====================================================================
// TF32 GEMM (mma.sync): C[M,N] = A[M,K] @ W[N,K]^T (+bias, rowscale, relu).
// CTA tile 256x128x32, 256 thr (8 warps, 4m x 2n, warp tile 64x64).
// 3-stage cp.async pipeline, ONE sync per k-chunk, fragment double buffer.
// smem/stage: A 256*36 + B 128*36 = 13824 words; 3 stages = 165888 B.
// =====================================================================
#define SKEW 36
#define A_W  (256*SKEW)
#define B_W  (128*SKEW)
#define STG_W (A_W + B_W)
#define GSMB (3*STG_W*4)

__global__ __launch_bounds__(256) void gemm_tf32_kernel(
    const uint32_t* __restrict__ A, const uint32_t* __restrict__ W,
    const float* __restrict__ bias, const float* __restrict__ rowscale,
    float* __restrict__ C, uint32_t* __restrict__ Ct,
    int M, int N, int K, int relu)
{
    extern __shared__ uint32_t sm[];
    const int tid = threadIdx.x;
    const int lane = tid & 31, warp = tid >> 5;
    const int wm = warp & 3, wn = warp >> 2;
    const int g = lane >> 2, tig = lane & 3;
    const int bx = blockIdx.x, by = blockIdx.y;

    float d[4][8][4];
    #pragma unroll
    for (int mt = 0; mt < 4; mt++)
        #pragma unroll
        for (int nt = 0; nt < 8; nt++)
            #pragma unroll
            for (int i = 0; i < 4; i++) d[mt][nt][i] = 0.f;

    uint32_t smbase = (uint32_t)__cvta_generic_to_shared(sm);
    uint32_t dstA[8], dstB[4];
    const uint32_t *aS[8], *wS[4];
    #pragma unroll
    for (int i = 0; i < 8; i++) {
        int f = tid + (i << 8);
        int r = f >> 3, c4 = (f & 7) << 2;
        dstA[i] = (uint32_t)(r * SKEW + c4) * 4;
        aS[i] = A + (size_t)(by * 256 + r) * K + c4;
    }
    #pragma unroll
    for (int i = 0; i < 4; i++) {
        int f = tid + (i << 8);
        int r = f >> 3, c4 = (f & 7) << 2;
        dstB[i] = (uint32_t)(A_W + r * SKEW + c4) * 4;
        wS[i] = W + (size_t)(bx * 128 + r) * K + c4;
    }

    auto issue = [&](int k0, int stg) {
        uint32_t b = smbase + (uint32_t)stg * (STG_W * 4);
        #pragma unroll
        for (int i = 0; i < 8; i++)
            asm volatile("cp.async.cg.shared.global [%0], [%1], 16;"
                         :: "r"(b + dstA[i]), "l"(aS[i] + k0) : "memory");
        #pragma unroll
        for (int i = 0; i < 4; i++)
            asm volatile("cp.async.cg.shared.global [%0], [%1], 16;"
                         :: "r"(b + dstB[i]), "l"(wS[i] + k0) : "memory");
        asm volatile("cp.async.commit_group;" ::: "memory");
    };

    const int arBase = wm * 64 + g;
    const int bcBase = wn * 64 + g;

    // fragment double buffer
    uint32_t af[2][4][4];
    uint32_t bf[2][8][2];
    auto load_frags = [&](const uint32_t* Ab, const uint32_t* Wb, int ks, int fb) {
        int kb = ks * 8;
        #pragma unroll
        for (int mt = 0; mt < 4; mt++) {
            int ar = arBase + mt * 16;
            af[fb][mt][0] = Ab[ar * SKEW + kb + tig];
            af[fb][mt][1] = Ab[(ar + 8) * SKEW + kb + tig];
            af[fb][mt][2] = Ab[ar * SKEW + kb + tig + 4];
            af[fb][mt][3] = Ab[(ar + 8) * SKEW + kb + tig + 4];
        }
        #pragma unroll
        for (int nt = 0; nt < 8; nt++) {
            int bc = bcBase + nt * 8;
            bf[fb][nt][0] = Wb[bc * SKEW + kb + tig];
            bf[fb][nt][1] = Wb[bc * SKEW + kb + tig + 4];
        }
    };
    auto mma_frags = [&](int fb) {
        #pragma unroll
        for (int nt = 0; nt < 8; nt++) {
            uint32_t b0 = bf[fb][nt][0], b1 = bf[fb][nt][1];
            #pragma unroll
            for (int mt = 0; mt < 4; mt++)
                mma_tf32(d[mt][nt], af[fb][mt], b0, b1);
        }
    };

    const int nch = K >> 5;
    issue(0, 0);
    issue(32, 1);

    int s0i = 0;   // stage of chunk ic
    for (int ic = 0; ic < nch; ic++) {
        if (ic + 1 < nch) {
            asm volatile("cp.async.wait_group 1;" ::: "memory");
        } else {
            asm volatile("cp.async.wait_group 0;" ::: "memory");
        }
        __syncthreads();
        // safe to refill the stage everyone finished reading at chunk ic-1
        if (ic + 2 < nch) {
            int s2 = s0i + 2; if (s2 >= 3) s2 -= 3;
            issue((ic + 2) << 5, s2);
        }

        const uint32_t* Ab = sm + s0i * STG_W;
        const uint32_t* Wb = Ab + A_W;
        load_frags(Ab, Wb, 0, 0);
        #pragma unroll
        for (int ks = 0; ks < 4; ks++) {
            if (ks < 3) load_frags(Ab, Wb, ks + 1, (ks + 1) & 1);
            mma_frags(ks & 1);
        }
        s0i = (s0i + 1 == 3) ? 0 : s0i + 1;
    }

    #pragma unroll
    for (int mt = 0; mt < 4; mt++) {
        int row0 = by * 256 + wm * 64 + mt * 16 + g;
        float rs0 = rowscale ? rowscale[row0] : 1.f;
        float rs1 = rowscale ? rowscale[row0 + 8] : 1.f;
        #pragma unroll
        for (int nt = 0; nt < 8; nt++) {
            int col = bx * 128 + wn * 64 + nt * 8 + tig * 2;
            float b0 = bias[col], b1 = bias[col + 1];
            float v00 = d[mt][nt][0] * rs0 + b0, v01 = d[mt][nt][1] * rs0 + b1;
            float v10 = d[mt][nt][2] * rs1 + b0, v11 = d[mt][nt][3] * rs1 + b1;
            if (relu) {
                v00 = fmaxf(v00, 0.f); v01 = fmaxf(v01, 0.f);
                v10 = fmaxf(v10, 0.f); v11 = fmaxf(v11, 0.f);
            }
            size_t o0 = (size_t)row0 * N + col;
            size_t o1 = (size_t)(row0 + 8) * N + col;
            if (C) {
                *(float2*)(C + o0) = make_float2(v00, v01);
                *(float2*)(C + o1) = make_float2(v10, v11);
            }
            if (Ct) {
                *(uint2*)(Ct + o0) = make_uint2(f2tf32(v00), f2tf32(v01));
                *(uint2*)(Ct + o1) = make_uint2(f2tf32(v10), f2tf32(v11));
            }
        }
    }
}

// =====================================================================
// Fused flash attention (tf32, mma.sync) — unchanged.
// =====================================================================
#define FQ 0
#define FK 8192
#define FV 16384
#define FP 26624
#define FL_SMEM_WORDS 43008

__global__ __launch_bounds__(256) void flash_tf32_kernel(
    const uint32_t* __restrict__ Q, const uint32_t* __restrict__ Kk,
    const uint32_t* __restrict__ V, const float* __restrict__ mask,
    uint32_t* __restrict__ ctx_t, float* __restrict__ attn, int causal)
{
    extern __shared__ uint32_t sm[];
    uint32_t* Qs = sm + FQ;
    uint32_t* Ks = sm + FK;
    uint32_t* Vs = sm + FV;
    const int tid = threadIdx.x;
    const int lane = tid & 31, warp = tid >> 5;
    const int g = lane >> 2, tig = lane & 3;
    const int bh = blockIdx.y;
    const int b = bh / HH, h = bh % HH;
    const int t0 = blockIdx.x * 128;
    const int wr0 = warp * 16;
    uint32_t* Pw = sm + FP + warp * 2048;

    #pragma unroll
    for (int i = 0; i < 8; i++) {
        int f = tid + (i << 8);
        int r = f >> 4;
        int c4 = (f & 15) << 2;
        int bse = ((c4 >> 3) << 10) + (r << 3) + ((c4 >> 2) & 1);
        uint4 q4 = *(const uint4*)(Q + ((size_t)(t0 + r) * BB + b) * DD + h * HDD + c4);
        Qs[bse + 0] = q4.x; Qs[bse + 2] = q4.y;
        Qs[bse + 4] = q4.z; Qs[bse + 6] = q4.w;
    }

    float mA = -1e30f, mB = -1e30f, lA = 0.f, lB = 0.f;
    float o[8][4];
    #pragma unroll
    for (int nt = 0; nt < 8; nt++)
        #pragma unroll
        for (int i = 0; i < 4; i++) o[nt][i] = 0.f;

    const int pe = ((tig * 2) & 3) * 2 + (tig >> 1);
    const int n_stiles = causal ? (blockIdx.x + 1) : (SSZ / 128);

    for (int is = 0; is < n_stiles; is++) {
        int s0 = is * 128;
        __syncthreads();

        #pragma unroll
        for (int i = 0; i < 8; i++) {
            int f = tid + (i << 8);
            int r = f >> 4;
            int c4 = (f & 15) << 2;
            int bse = ((c4 >> 3) << 10) + (r << 3) + ((c4 >> 2) & 1);
            uint4 k4 = *(const uint4*)(Kk + ((size_t)(s0 + r) * BB + b) * DD + h * HDD + c4);
            Ks[bse + 0] = k4.x; Ks[bse + 2] = k4.y;
            Ks[bse + 4] = k4.z; Ks[bse + 6] = k4.w;
            uint4 v4 = *(const uint4*)(V + ((size_t)(s0 + r) * BB + b) * DD + h * HDD + c4);
            int vb = ((r >> 3) * 640) + ((r & 3) << 1) + ((r >> 2) & 1);
            Vs[vb + (c4 + 0) * 10] = v4.x;
            Vs[vb + (c4 + 1) * 10] = v4.y;
            Vs[vb + (c4 + 2) * 10] = v4.z;
            Vs[vb + (c4 + 3) * 10] = v4.w;
        }
        __syncthreads();

        float s[16][4];
        #pragma unroll
        for (int nt = 0; nt < 16; nt++)
            #pragma unroll
            for (int i = 0; i < 4; i++) s[nt][i] = 0.f;

        #pragma unroll
        for (int ks = 0; ks < 8; ks++) {
            int ab = ks << 10;
            uint2 a0 = *(const uint2*)&Qs[ab + (wr0 + g) * 8 + tig * 2];
            uint2 a1 = *(const uint2*)&Qs[ab + (wr0 + 8 + g) * 8 + tig * 2];
            uint32_t af[4] = {a0.x, a1.x, a0.y, a1.y};
            #pragma unroll
            for (int nt = 0; nt < 16; nt++) {
                uint2 bb = *(const uint2*)&Ks[ab + (nt * 8 + g) * 8 + tig * 2];
                mma_tf32(s[nt], af, bb.x, bb.y);
            }
        }

        const float scale = 0.125f;
        if (causal && is == blockIdx.x) {
            int tAr = t0 + wr0 + g, tBr = tAr + 8;
            #pragma unroll
            for (int nt = 0; nt < 16; nt++) {
                int c = s0 + nt * 8 + tig * 2;
                s[nt][0] = s[nt][0] * scale + mask[(size_t)tAr * TT + c];
                s[nt][1] = s[nt][1] * scale + mask[(size_t)tAr * TT + c + 1];
                s[nt][2] = s[nt][2] * scale + mask[(size_t)tBr * TT + c];
                s[nt][3] = s[nt][3] * scale + mask[(size_t)tBr * TT + c + 1];
            }
        } else {
            #pragma unroll
            for (int nt = 0; nt < 16; nt++)
                #pragma unroll
                for (int i = 0; i < 4; i++) s[nt][i] *= scale;
        }

        float mtA = -1e30f, mtB = -1e30f;
        #pragma unroll
        for (int nt = 0; nt < 16; nt++) {
            mtA = fmaxf(mtA, fmaxf(s[nt][0], s[nt][1]));
            mtB = fmaxf(mtB, fmaxf(s[nt][2], s[nt][3]));
        }
        mtA = fmaxf(mtA, __shfl_xor_sync(0xffffffffu, mtA, 1));
        mtA = fmaxf(mtA, __shfl_xor_sync(0xffffffffu, mtA, 2));
        mtB = fmaxf(mtB, __shfl_xor_sync(0xffffffffu, mtB, 1));
        mtB = fmaxf(mtB, __shfl_xor_sync(0xffffffffu, mtB, 2));

        float mnA = fmaxf(mA, mtA), mnB = fmaxf(mB, mtB);
        float alA = __expf(mA - mnA), alB = __expf(mB - mnB);
        float rsA = 0.f, rsB = 0.f;
        #pragma unroll
        for (int nt = 0; nt < 16; nt++) {
            s[nt][0] = __expf(s[nt][0] - mnA);
            s[nt][1] = __expf(s[nt][1] - mnA);
            s[nt][2] = __expf(s[nt][2] - mnB);
            s[nt][3] = __expf(s[nt][3] - mnB);
            rsA += s[nt][0] + s[nt][1];
            rsB += s[nt][2] + s[nt][3];
        }
        rsA += __shfl_xor_sync(0xffffffffu, rsA, 1);
        rsA += __shfl_xor_sync(0xffffffffu, rsA, 2);
        rsB += __shfl_xor_sync(0xffffffffu, rsB, 1);
        rsB += __shfl_xor_sync(0xffffffffu, rsB, 2);
        lA = lA * alA + rsA; mA = mnA;
        lB = lB * alB + rsB; mB = mnB;

        #pragma unroll
        for (int nt = 0; nt < 8; nt++) {
            o[nt][0] *= alA; o[nt][1] *= alA;
            o[nt][2] *= alB; o[nt][3] *= alB;
        }

        __syncwarp();
        #pragma unroll
        for (int nt = 0; nt < 16; nt++) {
            int base = (nt << 7) + g * 8 + pe;
            Pw[base]          = f2tf32(s[nt][0]);
            Pw[base + 2]      = f2tf32(s[nt][1]);
            Pw[base + 64]     = f2tf32(s[nt][2]);
            Pw[base + 64 + 2] = f2tf32(s[nt][3]);
        }
        __syncwarp();

        #pragma unroll
        for (int ks = 0; ks < 16; ks++) {
            uint2 a0 = *(const uint2*)&Pw[(ks << 7) + g * 8 + tig * 2];
            uint2 a1 = *(const uint2*)&Pw[(ks << 7) + (g + 8) * 8 + tig * 2];
            uint32_t af[4] = {a0.x, a1.x, a0.y, a1.y};
            #pragma unroll
            for (int nt = 0; nt < 8; nt++) {
                uint2 bb = *(const uint2*)&Vs[ks * 640 + (nt * 8 + g) * 10 + tig * 2];
                mma_tf32(o[nt], af, bb.x, bb.y);
            }
        }
    }

    float invA = 1.f / lA, invB = 1.f / lB;
    int tA = t0 + wr0 + g, tB = tA + 8;
    #pragma unroll
    for (int nt = 0; nt < 8; nt++) {
        int hd = nt * 8 + tig * 2;
        float a0 = o[nt][0] * invA, a1 = o[nt][1] * invA;
        float b0 = o[nt][2] * invB, b1 = o[nt][3] * invB;
        *(uint2*)(ctx_t + ((size_t)tA * BB + b) * DD + h * HDD + hd) = make_uint2(f2tf32(a0), f2tf32(a1));
        *(uint2*)(ctx_t + ((size_t)tB * BB + b) * DD + h * HDD + hd) = make_uint2(f2tf32(b0), f2tf32(b1));
        if (attn) {
            *(float2*)(attn + (((size_t)h * BB + b) * TT + tA) * HDD + hd) = make_float2(a0, a1);
            *(float2*)(attn + (((size_t)h * BB + b) * TT + tB) * HDD + hd) = make_float2(b0, b1);
        }
    }
}

// ---------------- fused residual add + layernorm (optional tf32 dual store)
__global__ __launch_bounds__(256) void add_ln_kernel(
    const float* __restrict__ a, const float* __restrict__ r,
    const float* __restrict__ g, const float* __restrict__ be,
    float* __restrict__ o, uint32_t* __restrict__ ot)
{
    size_t row = blockIdx.x;
    int tid = threadIdx.x;
    float4 va = *(const float4*)(a + row * DD + tid * 4);
    float4 vr = *(const float4*)(r + row * DD + tid * 4);
    float x0 = va.x + vr.x, x1 = va.y + vr.y, x2 = va.z + vr.z, x3 = va.w + vr.w;
    float s  = block_sum(x0 + x1 + x2 + x3);
    float mu = s * (1.f / DD);
    float d0 = x0 - mu, d1 = x1 - mu, d2 = x2 - mu, d3 = x3 - mu;
    float sq = block_sum(d0 * d0 + d1 * d1 + d2 * d2 + d3 * d3);
    float inv = rsqrtf(sq * (1.f / DD) + 1e-5f);
    float4 vg = *(const float4*)(g + tid * 4);
    float4 vb = *(const float4*)(be + tid * 4);
    float4 out;
    out.x = d0 * inv * vg.x + vb.x;
    out.y = d1 * inv * vg.y + vb.y;
    out.z = d2 * inv * vg.z + vb.z;
    out.w = d3 * inv * vg.w + vb.w;
    *(float4*)(o + row * DD + tid * 4) = out;
    if (ot) {
        uint4 t;
        t.x = f2tf32(out.x); t.y = f2tf32(out.y);
        t.z = f2tf32(out.z); t.w = f2tf32(out.w);
        *(uint4*)(ot + row * DD + tid * 4) = t;
    }
}

// ---------------- host launch ----------------
extern "C" void kernel_launch(void* const* d_in, const int* in_sizes, int n_in,
                              void* d_out, int out_size)
{
    const float* state = (const float*)d_in[0];
    const float* enc   = (const float*)d_in[1];
    const float* amask = (const float*)d_in[2];
    const int* spad = (const int*)d_in[3];
    const int* epad = (const int*)d_in[4];
    const float *saWq = (const float*)d_in[5],  *sabq = (const float*)d_in[6];
    const float *saWk = (const float*)d_in[7],  *sabk = (const float*)d_in[8];
    const float *saWv = (const float*)d_in[9],  *sabv = (const float*)d_in[10];
    const float *saWo = (const float*)d_in[11], *sabo = (const float*)d_in[12];
    const float *eaWq = (const float*)d_in[13], *eabq = (const float*)d_in[14];
    const float *eaWk = (const float*)d_in[15], *eabk = (const float*)d_in[16];
    const float *eaWv = (const float*)d_in[17], *eabv = (const float*)d_in[18];
    const float *eaWo = (const float*)d_in[19], *eabo = (const float*)d_in[20];
    const float *ln1g = (const float*)d_in[21], *ln1b = (const float*)d_in[22];
    const float *ln2g = (const float*)d_in[23], *ln2b = (const float*)d_in[24];
    const float *ln3g = (const float*)d_in[25], *ln3b = (const float*)d_in[26];
    const float *fc1W = (const float*)d_in[27], *fc1b = (const float*)d_in[28];
    const float *fc2W = (const float*)d_in[29], *fc2b = (const float*)d_in[30];

    uint32_t *state_t, *enc_t, *qt, *kt, *vt, *ctx_t, *x1t, *x2t, *ffn_t, *wtf;
    float *tmp, *x1, *x2, *rss, *rse;
    cudaGetSymbolAddress((void**)&state_t, g_state_t);
    cudaGetSymbolAddress((void**)&enc_t,   g_enc_t);
    cudaGetSymbolAddress((void**)&qt,  g_qt);
    cudaGetSymbolAddress((void**)&kt,  g_kt);
    cudaGetSymbolAddress((void**)&vt,  g_vt);
    cudaGetSymbolAddress((void**)&ctx_t, g_ctx_t);
    cudaGetSymbolAddress((void**)&tmp, g_tmp);
    cudaGetSymbolAddress((void**)&x1,  g_x1);
    cudaGetSymbolAddress((void**)&x1t, g_x1t);
    cudaGetSymbolAddress((void**)&x2,  g_x2);
    cudaGetSymbolAddress((void**)&x2t, g_x2t);
    cudaGetSymbolAddress((void**)&ffn_t, g_ffn_t);
    cudaGetSymbolAddress((void**)&rss, g_rs_self);
    cudaGetSymbolAddress((void**)&rse, g_rs_enc);
    cudaGetSymbolAddress((void**)&wtf, g_wtf);

    const int FSM = FL_SMEM_WORDS * 4;
    cudaFuncSetAttribute(gemm_tf32_kernel,  cudaFuncAttributeMaxDynamicSharedMemorySize, GSMB);
    cudaFuncSetAttribute(flash_tf32_kernel, cudaFuncAttributeMaxDynamicSharedMemorySize, FSM);

    float* outx = (float*)d_out;
    float* outa = outx + (size_t)MM * DD;

    // ---- pre-convert weights + input activations (one fused kernel) ----
    const int NW = DD * DD;
    const int NF = FFND * DD;
    const int NA = MM * DD;
    CvtJobs jobs;
    jobs.src[0] = saWq; jobs.dst[0] = wtf + WOFF_SAQ; jobs.n[0] = NW;
    jobs.src[1] = saWk; jobs.dst[1] = wtf + WOFF_SAK; jobs.n[1] = NW;
    jobs.src[2] = saWv; jobs.dst[2] = wtf + WOFF_SAV; jobs.n[2] = NW;
    jobs.src[3] = saWo; jobs.dst[3] = wtf + WOFF_SAO; jobs.n[3] = NW;
    jobs.src[4] = eaWq; jobs.dst[4] = wtf + WOFF_EAQ; jobs.n[4] = NW;
    jobs.src[5] = eaWk; jobs.dst[5] = wtf + WOFF_EAK; jobs.n[5] = NW;
    jobs.src[6] = eaWv; jobs.dst[6] = wtf + WOFF_EAV; jobs.n[6] = NW;
    jobs.src[7] = eaWo; jobs.dst[7] = wtf + WOFF_EAO; jobs.n[7] = NW;
    jobs.src[8] = fc1W; jobs.dst[8] = wtf + WOFF_FC1; jobs.n[8] = NF;
    jobs.src[9] = fc2W; jobs.dst[9] = wtf + WOFF_FC2; jobs.n[9] = NF;
    jobs.src[10] = state; jobs.dst[10] = state_t; jobs.n[10] = NA;
    jobs.src[11] = enc;   jobs.dst[11] = enc_t;   jobs.n[11] = NA;
    cvt_all_kernel<<<dim3(NF / 1024, 12), 256>>>(jobs);

    expand_mask_kernel<<<(MM + 255) / 256, 256>>>(spad, rss, TT);
    expand_mask_kernel<<<(MM + 255) / 256, 256>>>(epad, rse, SSZ);

    dim3 gP(DD / 128, MM / 256);        // 128 CTAs
    dim3 gF1(FFND / 128, MM / 256);
    dim3 gFl(TT / 128, BB * HH);

    // ---- self-attention ----
    gemm_tf32_kernel<<<gP, 256, GSMB>>>(state_t, wtf + WOFF_SAQ, sabq, nullptr, nullptr, qt, MM, DD, DD, 0);
    gemm_tf32_kernel<<<gP, 256, GSMB>>>(state_t, wtf + WOFF_SAK, sabk, rss,     nullptr, kt, MM, DD, DD, 0);
    gemm_tf32_kernel<<<gP, 256, GSMB>>>(state_t, wtf + WOFF_SAV, sabv, nullptr, nullptr, vt, MM, DD, DD, 0);
    flash_tf32_kernel<<<gFl, 256, FSM>>>(qt, kt, vt, amask, ctx_t, nullptr, 1);
    gemm_tf32_kernel<<<gP, 256, GSMB>>>(ctx_t, wtf + WOFF_SAO, sabo, nullptr, tmp, nullptr, MM, DD, DD, 0);
    add_ln_kernel<<<MM, 256>>>(tmp, state, ln1g, ln1b, x1, x1t);

    // ---- encoder-decoder attention ----
    gemm_tf32_kernel<<<gP, 256, GSMB>>>(x1t,   wtf + WOFF_EAQ, eabq, nullptr, nullptr, qt, MM, DD, DD, 0);
    gemm_tf32_kernel<<<gP, 256, GSMB>>>(enc_t, wtf + WOFF_EAK, eabk, rse,     nullptr, kt, MM, DD, DD, 0);
    gemm_tf32_kernel<<<gP, 256, GSMB>>>(enc_t, wtf + WOFF_EAV, eabv, nullptr, nullptr, vt, MM, DD, DD, 0);
    flash_tf32_kernel<<<gFl, 256, FSM>>>(qt, kt, vt, nullptr, ctx_t, outa, 0);
    gemm_tf32_kernel<<<gP, 256, GSMB>>>(ctx_t, wtf + WOFF_EAO, eabo, nullptr, tmp, nullptr, MM, DD, DD, 0);
    add_ln_kernel<<<MM, 256>>>(tmp, x1, ln2g, ln2b, x2, x2t);

    // ---- FFN ----
    gemm_tf32_kernel<<<gF1, 256, GSMB>>>(x2t,   wtf + WOFF_FC1, fc1b, nullptr, nullptr, ffn_t, MM, FFND, DD, 1);
    gemm_tf32_kernel<<<gP, 256, GSMB>>>(ffn_t, wtf + WOFF_FC2, fc2b, nullptr, tmp, nullptr, MM, DD, FFND, 0);
    add_ln_kernel<<<MM, 256>>>(tmp, x2, ln3g, ln3b, outx, nullptr);
}